// round 13
// baseline (speedup 1.0000x reference)
#include <cuda_runtime.h>
#include <math.h>

#define NPIX 4096

// ---------------- f32x2 packed helpers (sm_100+) ----------------
__device__ __forceinline__ unsigned long long pack2(float lo, float hi) {
    unsigned long long r;
    asm("mov.b64 %0, {%1, %2};" : "=l"(r) : "f"(lo), "f"(hi));
    return r;
}
__device__ __forceinline__ float2 unpack2(unsigned long long v) {
    float2 r;
    asm("mov.b64 {%0, %1}, %2;" : "=f"(r.x), "=f"(r.y) : "l"(v));
    return r;
}
__device__ __forceinline__ void fma2(unsigned long long& d, unsigned long long a, unsigned long long b) {
    asm("fma.rn.f32x2 %0, %1, %2, %3;" : "=l"(d) : "l"(a), "l"(b), "l"(d));
}

// ---------------- tf32 mma helpers ----------------
__device__ __forceinline__ unsigned tf32_of(float f) {
    unsigned r;
    asm("cvt.rna.tf32.f32 %0, %1;" : "=r"(r) : "f"(f));
    return r;
}
__device__ __forceinline__ void mma_tf32(float* d, const unsigned* a, unsigned b0, unsigned b1) {
    asm volatile(
        "mma.sync.aligned.m16n8k8.row.col.f32.tf32.tf32.f32 "
        "{%0,%1,%2,%3}, {%4,%5,%6,%7}, {%8,%9}, {%0,%1,%2,%3};"
        : "+f"(d[0]), "+f"(d[1]), "+f"(d[2]), "+f"(d[3])
        : "r"(a[0]), "r"(a[1]), "r"(a[2]), "r"(a[3]), "r"(b0), "r"(b1));
}

// ---------------- scratch (device globals; allocation forbidden) ----------------
__device__ __align__(128) float g_skip_u[4 * NPIX * 64];   // NHWC [b][n][c]
__device__ __align__(128) float g_mean  [4 * NPIX];
__device__ __align__(128) float g_thick [4 * NPIX];
__device__ __align__(128) float g_edge  [4 * NPIX * 64];   // NHWC [b][n][c]
__device__ __align__(128) float g_off   [4 * NPIX * 18];   // NHWC [b][n][18]
__device__ __align__(128) float g_d     [4 * 64 * NPIX];   // NCHW
__device__ __align__(128) float g_qkv   [4 * 96 * NPIX];
__device__ __align__(128) float g_av    [4 * 32 * NPIX];
__device__ __align__(128) float g_x2    [4 * 256 * NPIX];
__device__ __align__(128) float g_e     [4 * 64 * NPIX];
__device__ __align__(128) float g_h     [4 * 64 * NPIX];
__device__ __align__(128) float g_h1    [4 * 256 * NPIX];
__device__ __align__(128) float g_h2    [4 * 256 * NPIX];
__device__ __align__(128) float g_t     [4 * 64 * NPIX];
// transposed weights [IC][OC], pre-rounded to tf32
__device__ __align__(128) float g_qkvWT [256 * 96];
__device__ __align__(128) float g_projWT[32 * 256];
__device__ __align__(128) float g_downWT[320 * 64];
__device__ __align__(128) float g_mlp1WT[64 * 256];
__device__ __align__(128) float g_mlp2WT[256 * 64];
__device__ __align__(128) float g_upWT  [64 * 256];
__device__ __align__(128) float g_dwT   [9 * 64 * 64];   // deform_w as [k][c][o] (fp32)

// ---------------- prep: transpose weights (GEMM weights stored as tf32 bits) ----------------
__global__ void prep_kernel(const float* __restrict__ qkv_w, const float* __restrict__ proj_w,
                            const float* __restrict__ down_w, const float* __restrict__ mlp1_w,
                            const float* __restrict__ mlp2_w, const float* __restrict__ up_w,
                            const float* __restrict__ deform_w) {
    int t0 = blockIdx.x * blockDim.x + threadIdx.x;
    int stride = gridDim.x * blockDim.x;
    for (int i = t0; i < 256 * 96; i += stride) { int ic = i / 96,  oc = i % 96;  g_qkvWT[i]  = __uint_as_float(tf32_of(qkv_w[oc * 256 + ic])); }
    for (int i = t0; i < 32 * 256; i += stride) { int ic = i / 256, oc = i % 256; g_projWT[i] = __uint_as_float(tf32_of(proj_w[oc * 32 + ic])); }
    for (int i = t0; i < 320 * 64; i += stride) { int ic = i / 64,  oc = i % 64;  g_downWT[i] = __uint_as_float(tf32_of(down_w[oc * 320 + ic])); }
    for (int i = t0; i < 64 * 256; i += stride) { int ic = i / 256, oc = i % 256; g_mlp1WT[i] = __uint_as_float(tf32_of(mlp1_w[oc * 64 + ic])); }
    for (int i = t0; i < 256 * 64; i += stride) { int ic = i / 64,  oc = i % 64;  g_mlp2WT[i] = __uint_as_float(tf32_of(mlp2_w[oc * 256 + ic])); }
    for (int i = t0; i < 64 * 256; i += stride) { int ic = i / 256, oc = i % 256; g_upWT[i]   = __uint_as_float(tf32_of(up_w[oc * 64 + ic])); }
    for (int i = t0; i < 9 * 64 * 64; i += stride) {
        int k = i >> 12, c = (i >> 6) & 63, o = i & 63;
        g_dwT[i] = deform_w[(o * 64 + c) * 9 + k];
    }
}

// ---------------- bilinear upsample (half-pixel) + channel mean + thick (NHWC out) ----------------
__global__ void upsample_kernel(const float* __restrict__ skip, const float* __restrict__ thick_w,
                                const float* __restrict__ thick_b) {
    int b = blockIdx.y, y = blockIdx.x, x = threadIdx.x;
    float sy = fminf(fmaxf(0.5f * y - 0.25f, 0.f), 31.f);
    float sx = fminf(fmaxf(0.5f * x - 0.25f, 0.f), 31.f);
    int y0 = (int)sy, x0 = (int)sx;
    int y1 = min(y0 + 1, 31), x1 = min(x0 + 1, 31);
    float wy = sy - (float)y0, wx = sx - (float)x0;
    float w00 = (1.f - wy) * (1.f - wx), w01 = (1.f - wy) * wx;
    float w10 = wy * (1.f - wx),         w11 = wy * wx;
    const float* sp = skip + (size_t)b * 64 * 1024;
    int pix = b * NPIX + y * 64 + x;
    float* up = g_skip_u + (size_t)pix * 64;
    float sum = 0.f, tsum = 0.f;
    for (int c = 0; c < 64; c++) {
        const float* p = sp + c * 1024;
        float v = w00 * p[y0 * 32 + x0] + w01 * p[y0 * 32 + x1]
                + w10 * p[y1 * 32 + x0] + w11 * p[y1 * 32 + x1];
        up[c] = v;
        sum += v;
        tsum += v * thick_w[c];
    }
    g_mean[pix] = sum * (1.f / 64.f);
    g_thick[pix] = 1.f / (1.f + expf(-(tsum + thick_b[0])));
}

// ---------------- edge conv: 3x3, 1 -> 64 ch, zero pad, no bias (NHWC out) ----------------
__global__ void edge_kernel(const float* __restrict__ edge_w) {
    int idx = blockIdx.x * 256 + threadIdx.x;          // 4*4096*64, oc fastest
    int oc = idx & 63, n = (idx >> 6) & 4095, b = idx >> 18;
    int y = n >> 6, x = n & 63;
    const float* mp = g_mean + b * NPIX;
    float a = 0.f;
#pragma unroll
    for (int ky = 0; ky < 3; ky++) {
        int yy = y + ky - 1;
        if (yy < 0 || yy >= 64) continue;
#pragma unroll
        for (int kx = 0; kx < 3; kx++) {
            int xx = x + kx - 1;
            if (xx < 0 || xx >= 64) continue;
            a += mp[yy * 64 + xx] * edge_w[oc * 9 + ky * 3 + kx];
        }
    }
    g_edge[idx] = a;
}

// ---------------- offset conv: 3x3, 64 -> 18, * (1 + 16*thick) ----------------
// 512 threads: 64 pixels x 8 channel groups (8 ch each), smem-reduced. grid 256.
__global__ __launch_bounds__(512) void off_kernel(const float* __restrict__ off_w,
                                                  const float* __restrict__ off_b) {
    __shared__ float pool[64 * 9 * 18];                // ws, then reused as red[8*64*18]
    float* ws = pool;
    for (int i = threadIdx.x; i < 64 * 9 * 18; i += 512) {
        int o = i % 18, ck = i / 18;
        ws[i] = off_w[o * 576 + ck];                   // [c][k][o]
    }
    __syncthreads();
    int pl = threadIdx.x & 63, g = threadIdx.x >> 6;   // pixel-in-block, channel group
    int pix = blockIdx.x * 64 + pl;
    int b = pix >> 12, n = pix & 4095;
    int y = n >> 6, x = n & 63;
    unsigned long long acc[9];
#pragma unroll
    for (int o = 0; o < 9; o++) acc[o] = 0ull;
    const float* ep = g_edge + (size_t)b * NPIX * 64;
#pragma unroll
    for (int ky = 0; ky < 3; ky++) {
        int yy = y + ky - 1;
        if (yy < 0 || yy >= 64) continue;
#pragma unroll
        for (int kx = 0; kx < 3; kx++) {
            int xx = x + kx - 1;
            if (xx < 0 || xx >= 64) continue;
            int k = ky * 3 + kx;
            const float4* col = (const float4*)(ep + (size_t)(yy * 64 + xx) * 64 + g * 8);
#pragma unroll
            for (int c4 = 0; c4 < 2; c4++) {
                float4 v4 = col[c4];
#pragma unroll
                for (int cc = 0; cc < 4; cc++) {
                    float v = (cc == 0) ? v4.x : (cc == 1) ? v4.y : (cc == 2) ? v4.z : v4.w;
                    unsigned long long vd = pack2(v, v);
                    const unsigned long long* wr =
                        (const unsigned long long*)&ws[((g * 8 + c4 * 4 + cc) * 9 + k) * 18];
#pragma unroll
                    for (int o = 0; o < 9; o++) fma2(acc[o], vd, wr[o]);
                }
            }
        }
    }
    __syncthreads();                                   // done with ws reads
    float* red = pool;                                 // [8][64][18]
#pragma unroll
    for (int o = 0; o < 9; o++)
        *(float2*)&red[((g * 64 + pl) * 18) + 2 * o] = unpack2(acc[o]);
    __syncthreads();
    for (int i = threadIdx.x; i < 64 * 18; i += 512) {
        int p2 = i / 18, o = i % 18;
        float s = 0.f;
#pragma unroll
        for (int gg = 0; gg < 8; gg++) s += red[(gg * 64 + p2) * 18 + o];
        int gp = blockIdx.x * 64 + p2;
        float tscale = 1.f + 16.f * g_thick[gp];
        g_off[(size_t)gp * 18 + o] = (s + off_b[o]) * tscale;
    }
}

// ---------------- deformable conv 3x3 (DCNv1) + bias + edge ----------------
// 128 threads: 64 pixels x 2 out-channel halves (32 ch each). grid 256.
__global__ __launch_bounds__(128) void deform_kernel(const float* __restrict__ deform_b) {
    __shared__ float ws[4096];                         // [c][o] for current tap
    int pl = threadIdx.x & 63, half = threadIdx.x >> 6;
    int pix = blockIdx.x * 64 + pl;
    int b = pix >> 12, n = pix & 4095;
    int y = n >> 6, x = n & 63;
    unsigned long long acc[16];
#pragma unroll
    for (int o = 0; o < 16; o++) acc[o] = 0ull;
    const float* su = g_skip_u + (size_t)b * NPIX * 64;
    const float* offp = g_off + (size_t)pix * 18;
    for (int k = 0; k < 9; k++) {
        __syncthreads();
        for (int i = threadIdx.x * 4; i < 4096; i += 128 * 4)
            *(float4*)&ws[i] = *(const float4*)&g_dwT[k * 4096 + i];
        __syncthreads();
        float py = (float)(y + k / 3 - 1) + offp[2 * k];
        float px = (float)(x + k % 3 - 1) + offp[2 * k + 1];
        float y0f = floorf(py), x0f = floorf(px);
        float wy = py - y0f, wx = px - x0f;
        int y0 = (int)y0f, x0 = (int)x0f;
        int y1 = y0 + 1, x1 = x0 + 1;
        bool vy0 = (y0 >= 0 && y0 < 64), vy1 = (y1 >= 0 && y1 < 64);
        bool vx0 = (x0 >= 0 && x0 < 64), vx1 = (x1 >= 0 && x1 < 64);
        float w00 = (vy0 && vx0) ? (1.f - wy) * (1.f - wx) : 0.f;
        float w01 = (vy0 && vx1) ? (1.f - wy) * wx : 0.f;
        float w10 = (vy1 && vx0) ? wy * (1.f - wx) : 0.f;
        float w11 = (vy1 && vx1) ? wy * wx : 0.f;
        int yc0 = min(max(y0, 0), 63), yc1 = min(max(y1, 0), 63);
        int xc0 = min(max(x0, 0), 63), xc1 = min(max(x1, 0), 63);
        const float4* p00 = (const float4*)(su + (size_t)(yc0 * 64 + xc0) * 64);
        const float4* p01 = (const float4*)(su + (size_t)(yc0 * 64 + xc1) * 64);
        const float4* p10 = (const float4*)(su + (size_t)(yc1 * 64 + xc0) * 64);
        const float4* p11 = (const float4*)(su + (size_t)(yc1 * 64 + xc1) * 64);
        for (int c4 = 0; c4 < 16; c4++) {
            float4 a0 = p00[c4], a1 = p01[c4], a2 = p10[c4], a3 = p11[c4];
            float4 val4;
            val4.x = w00 * a0.x + w01 * a1.x + w10 * a2.x + w11 * a3.x;
            val4.y = w00 * a0.y + w01 * a1.y + w10 * a2.y + w11 * a3.y;
            val4.z = w00 * a0.z + w01 * a1.z + w10 * a2.z + w11 * a3.z;
            val4.w = w00 * a0.w + w01 * a1.w + w10 * a2.w + w11 * a3.w;
#pragma unroll
            for (int cc = 0; cc < 4; cc++) {
                float v = (cc == 0) ? val4.x : (cc == 1) ? val4.y : (cc == 2) ? val4.z : val4.w;
                unsigned long long vd = pack2(v, v);
                const unsigned long long* wr =
                    (const unsigned long long*)&ws[(c4 * 4 + cc) * 64 + half * 32];
#pragma unroll
                for (int o = 0; o < 16; o++) fma2(acc[o], vd, wr[o]);
            }
        }
    }
    const float* ep = g_edge + (size_t)pix * 64 + half * 32;
    float* dp = g_d + (size_t)b * 64 * NPIX + (size_t)(half * 32) * NPIX + n;
    const float* db = deform_b + half * 32;
#pragma unroll
    for (int o2 = 0; o2 < 16; o2++) {
        float2 a2 = unpack2(acc[o2]);
        dp[(size_t)(2 * o2 + 0) * NPIX] = a2.x + db[2 * o2 + 0] + ep[2 * o2 + 0];
        dp[(size_t)(2 * o2 + 1) * NPIX] = a2.y + db[2 * o2 + 1] + ep[2 * o2 + 1];
    }
}

// ---------------- 1x1-conv GEMM on tensor cores (tf32 mma.sync) ----------------
__global__ __launch_bounds__(256) void gemm_tf32(const float* __restrict__ inA, int icA,
                                                 const float* __restrict__ inB, int IC,
                                                 const float* __restrict__ WT,
                                                 const float* __restrict__ bias, int OC,
                                                 const float* __restrict__ res,
                                                 float* __restrict__ out, int act) {
    __shared__ float Bs[16][136];
    __shared__ float Ws[16][72];
    int tid = threadIdx.x;
    int lane = tid & 31, w = tid >> 5;
    int g = lane >> 2, t = lane & 3;
    int wm = w >> 2, wn = w & 3;
    int n0 = blockIdx.x * 128;
    int oc0 = blockIdx.y * 64;
    int lb = n0 >> 12, ln = n0 & 4095;
    int icB = IC - icA;

    float acc[2][4][4];
#pragma unroll
    for (int mt = 0; mt < 2; mt++)
#pragma unroll
        for (int nt = 0; nt < 4; nt++)
#pragma unroll
            for (int j = 0; j < 4; j++) acc[mt][nt][j] = 0.f;

    int brow = tid >> 4, bcol = (tid & 15) * 8;
    int wrow = tid >> 4, wcol = (tid & 15) * 4;

    for (int k0 = 0; k0 < IC; k0 += 16) {
        __syncthreads();
        {
            int ic = k0 + brow;
            const float* src;
            if (ic < icA) src = inA + ((size_t)lb * icA + ic) * NPIX + ln + bcol;
            else          src = inB + ((size_t)lb * icB + (ic - icA)) * NPIX + ln + bcol;
            float4 v0 = *(const float4*)src;
            float4 v1 = *(const float4*)(src + 4);
            float4 s0, s1;
            s0.x = __uint_as_float(tf32_of(v0.x)); s0.y = __uint_as_float(tf32_of(v0.y));
            s0.z = __uint_as_float(tf32_of(v0.z)); s0.w = __uint_as_float(tf32_of(v0.w));
            s1.x = __uint_as_float(tf32_of(v1.x)); s1.y = __uint_as_float(tf32_of(v1.y));
            s1.z = __uint_as_float(tf32_of(v1.z)); s1.w = __uint_as_float(tf32_of(v1.w));
            *(float4*)&Bs[brow][bcol] = s0;
            *(float4*)&Bs[brow][bcol + 4] = s1;
        }
        {
            const float* wsrc = WT + (size_t)(k0 + wrow) * OC + oc0 + wcol;
            float4 wv;
            if (oc0 + wcol + 3 < OC) {
                wv = *(const float4*)wsrc;
            } else {
                wv.x = (oc0 + wcol + 0 < OC) ? wsrc[0] : 0.f;
                wv.y = (oc0 + wcol + 1 < OC) ? wsrc[1] : 0.f;
                wv.z = (oc0 + wcol + 2 < OC) ? wsrc[2] : 0.f;
                wv.w = (oc0 + wcol + 3 < OC) ? wsrc[3] : 0.f;
            }
            *(float4*)&Ws[wrow][wcol] = wv;   // weights pre-rounded to tf32 in prep
        }
        __syncthreads();
#pragma unroll
        for (int ks = 0; ks < 2; ks++) {
            int kb = ks * 8;
            unsigned af[2][4];
#pragma unroll
            for (int mt = 0; mt < 2; mt++) {
                int row = wm * 32 + mt * 16;
                af[mt][0] = __float_as_uint(Ws[kb + t][row + g]);
                af[mt][1] = __float_as_uint(Ws[kb + t][row + g + 8]);
                af[mt][2] = __float_as_uint(Ws[kb + t + 4][row + g]);
                af[mt][3] = __float_as_uint(Ws[kb + t + 4][row + g + 8]);
            }
#pragma unroll
            for (int nt = 0; nt < 4; nt++) {
                int col = wn * 32 + nt * 8 + g;
                unsigned b0 = __float_as_uint(Bs[kb + t][col]);
                unsigned b1 = __float_as_uint(Bs[kb + t + 4][col]);
                mma_tf32(acc[0][nt], af[0], b0, b1);
                mma_tf32(acc[1][nt], af[1], b0, b1);
            }
        }
    }
#pragma unroll
    for (int mt = 0; mt < 2; mt++) {
#pragma unroll
        for (int nt = 0; nt < 4; nt++) {
            int col = ln + wn * 32 + nt * 8 + 2 * t;
#pragma unroll
            for (int r = 0; r < 2; r++) {
                int oc = oc0 + wm * 32 + mt * 16 + g + r * 8;
                if (oc < OC) {
                    float v0 = acc[mt][nt][r * 2 + 0] + bias[oc];
                    float v1 = acc[mt][nt][r * 2 + 1] + bias[oc];
                    if (act) { v0 = v0 * normcdff(v0); v1 = v1 * normcdff(v1); }
                    size_t oi = ((size_t)lb * OC + oc) * NPIX + col;
                    if (res) { v0 += res[oi]; v1 += res[oi + 1]; }
                    *(float2*)&out[oi] = make_float2(v0, v1);
                }
            }
        }
    }
}

// ---------------- down GEMM (IC=320, OC=64) fused with LayerNorm ----------------
// Writes e = conv result (g_e) and h = LN(e) (g_h). One block = 64 oc x 128 pix.
__global__ __launch_bounds__(256) void gemm_down_ln(const float* __restrict__ inA,
                                                    const float* __restrict__ inB,
                                                    const float* __restrict__ WT,
                                                    const float* __restrict__ bias,
                                                    const float* __restrict__ ln_g,
                                                    const float* __restrict__ ln_b) {
    __shared__ float Bs[16][136];
    __shared__ float Ws[16][72];
    __shared__ float Cs[64 * 133];        // [oc][pix], stride 133 (conflict-free cols)
    const int IC = 320, icA = 256, OC = 64;
    int tid = threadIdx.x;
    int lane = tid & 31, w = tid >> 5;
    int g = lane >> 2, t = lane & 3;
    int wm = w >> 2, wn = w & 3;
    int n0 = blockIdx.x * 128;
    int lb = n0 >> 12, ln = n0 & 4095;
    int icB = IC - icA;

    float acc[2][4][4];
#pragma unroll
    for (int mt = 0; mt < 2; mt++)
#pragma unroll
        for (int nt = 0; nt < 4; nt++)
#pragma unroll
            for (int j = 0; j < 4; j++) acc[mt][nt][j] = 0.f;

    int brow = tid >> 4, bcol = (tid & 15) * 8;
    int wrow = tid >> 4, wcol = (tid & 15) * 4;

    for (int k0 = 0; k0 < IC; k0 += 16) {
        __syncthreads();
        {
            int ic = k0 + brow;
            const float* src;
            if (ic < icA) src = inA + ((size_t)lb * icA + ic) * NPIX + ln + bcol;
            else          src = inB + ((size_t)lb * icB + (ic - icA)) * NPIX + ln + bcol;
            float4 v0 = *(const float4*)src;
            float4 v1 = *(const float4*)(src + 4);
            float4 s0, s1;
            s0.x = __uint_as_float(tf32_of(v0.x)); s0.y = __uint_as_float(tf32_of(v0.y));
            s0.z = __uint_as_float(tf32_of(v0.z)); s0.w = __uint_as_float(tf32_of(v0.w));
            s1.x = __uint_as_float(tf32_of(v1.x)); s1.y = __uint_as_float(tf32_of(v1.y));
            s1.z = __uint_as_float(tf32_of(v1.z)); s1.w = __uint_as_float(tf32_of(v1.w));
            *(float4*)&Bs[brow][bcol] = s0;
            *(float4*)&Bs[brow][bcol + 4] = s1;
        }
        *(float4*)&Ws[wrow][wcol] = *(const float4*)(WT + (size_t)(k0 + wrow) * OC + wcol);
        __syncthreads();
#pragma unroll
        for (int ks = 0; ks < 2; ks++) {
            int kb = ks * 8;
            unsigned af[2][4];
#pragma unroll
            for (int mt = 0; mt < 2; mt++) {
                int row = wm * 32 + mt * 16;
                af[mt][0] = __float_as_uint(Ws[kb + t][row + g]);
                af[mt][1] = __float_as_uint(Ws[kb + t][row + g + 8]);
                af[mt][2] = __float_as_uint(Ws[kb + t + 4][row + g]);
                af[mt][3] = __float_as_uint(Ws[kb + t + 4][row + g + 8]);
            }
#pragma unroll
            for (int nt = 0; nt < 4; nt++) {
                int col = wn * 32 + nt * 8 + g;
                unsigned b0 = __float_as_uint(Bs[kb + t][col]);
                unsigned b1 = __float_as_uint(Bs[kb + t + 4][col]);
                mma_tf32(acc[0][nt], af[0], b0, b1);
                mma_tf32(acc[1][nt], af[1], b0, b1);
            }
        }
    }
    __syncthreads();                       // done with Bs/Ws; epilogue writes e + Cs
#pragma unroll
    for (int mt = 0; mt < 2; mt++) {
#pragma unroll
        for (int nt = 0; nt < 4; nt++) {
            int lcol = wn * 32 + nt * 8 + 2 * t;
#pragma unroll
            for (int r = 0; r < 2; r++) {
                int oc = wm * 32 + mt * 16 + g + r * 8;
                float v0 = acc[mt][nt][r * 2 + 0] + bias[oc];
                float v1 = acc[mt][nt][r * 2 + 1] + bias[oc];
                size_t oi = ((size_t)lb * 64 + oc) * NPIX + ln + lcol;
                *(float2*)&g_e[oi] = make_float2(v0, v1);
                Cs[oc * 133 + lcol] = v0;
                Cs[oc * 133 + lcol + 1] = v1;
            }
        }
    }
    __syncthreads();
    if (tid < 128) {                       // per-pixel LayerNorm over 64 channels
        float v[64], mu = 0.f;
#pragma unroll
        for (int c = 0; c < 64; c++) { v[c] = Cs[c * 133 + tid]; mu += v[c]; }
        mu *= (1.f / 64.f);
        float var = 0.f;
#pragma unroll
        for (int c = 0; c < 64; c++) { float d2 = v[c] - mu; var += d2 * d2; }
        var *= (1.f / 64.f);
        float inv = rsqrtf(var + 1e-5f);
        float* hp = g_h + (size_t)lb * 64 * NPIX + ln + tid;
#pragma unroll
        for (int c = 0; c < 64; c++)
            hp[(size_t)c * NPIX] = (v[c] - mu) * inv * ln_g[c] + ln_b[c];
    }
}

// ---------------- flash attention (tf32 mma.sync): N=4096, d=32 per batch ----------------
__global__ __launch_bounds__(128) void flash_kernel() {
    __shared__ float Kt_s[32 * 72];        // [ch][key]
    __shared__ float Vs_s[64 * 41];        // [key][ch]
    __shared__ float Ps_s[4 * 16 * 72];    // per-warp P tile
    int b = blockIdx.y;
    int q0 = blockIdx.x * 64;
    int tid = threadIdx.x;
    int w = tid >> 5, lane = tid & 31;
    int g = lane >> 2, t = lane & 3;
    const float* qkv = g_qkv + (size_t)b * 96 * NPIX;
    const float QSCALE = 1.4426950408889634f * 0.17677669529663687f;
    int qrow = q0 + w * 16 + g;

    unsigned qa[4][4];
#pragma unroll
    for (int kc = 0; kc < 4; kc++) {
        qa[kc][0] = tf32_of(qkv[(size_t)(kc * 8 + t) * NPIX + qrow] * QSCALE);
        qa[kc][1] = tf32_of(qkv[(size_t)(kc * 8 + t) * NPIX + qrow + 8] * QSCALE);
        qa[kc][2] = tf32_of(qkv[(size_t)(kc * 8 + t + 4) * NPIX + qrow] * QSCALE);
        qa[kc][3] = tf32_of(qkv[(size_t)(kc * 8 + t + 4) * NPIX + qrow + 8] * QSCALE);
    }

    float m0 = -INFINITY, m1 = -INFINITY, l0 = 0.f, l1 = 0.f;
    float o[4][4];
#pragma unroll
    for (int i = 0; i < 4; i++)
#pragma unroll
        for (int j = 0; j < 4; j++) o[i][j] = 0.f;
    float* Pw = Ps_s + w * 16 * 72;

    for (int kt = 0; kt < 64; kt++) {
        int k0 = kt * 64;
        __syncthreads();
        for (int i = tid; i < 2048; i += 128) {
            int ch = i >> 6, key = i & 63;
            Kt_s[ch * 72 + key] = __uint_as_float(tf32_of(qkv[(size_t)(32 + ch) * NPIX + k0 + key]));
            Vs_s[key * 41 + ch] = __uint_as_float(tf32_of(qkv[(size_t)(64 + ch) * NPIX + k0 + key]));
        }
        __syncthreads();

        float s[8][4];
#pragma unroll
        for (int nt = 0; nt < 8; nt++)
#pragma unroll
            for (int j = 0; j < 4; j++) s[nt][j] = 0.f;
#pragma unroll
        for (int nt = 0; nt < 8; nt++) {
#pragma unroll
            for (int kc = 0; kc < 4; kc++) {
                unsigned b0 = __float_as_uint(Kt_s[(kc * 8 + t) * 72 + nt * 8 + g]);
                unsigned b1 = __float_as_uint(Kt_s[(kc * 8 + t + 4) * 72 + nt * 8 + g]);
                mma_tf32(s[nt], qa[kc], b0, b1);
            }
        }

        float pm0 = -INFINITY, pm1 = -INFINITY;
#pragma unroll
        for (int nt = 0; nt < 8; nt++) {
            pm0 = fmaxf(pm0, fmaxf(s[nt][0], s[nt][1]));
            pm1 = fmaxf(pm1, fmaxf(s[nt][2], s[nt][3]));
        }
        pm0 = fmaxf(pm0, __shfl_xor_sync(0xffffffffu, pm0, 1, 4));
        pm0 = fmaxf(pm0, __shfl_xor_sync(0xffffffffu, pm0, 2, 4));
        pm1 = fmaxf(pm1, __shfl_xor_sync(0xffffffffu, pm1, 1, 4));
        pm1 = fmaxf(pm1, __shfl_xor_sync(0xffffffffu, pm1, 2, 4));
        float mn0 = fmaxf(m0, pm0), mn1 = fmaxf(m1, pm1);
        float al0 = exp2f(m0 - mn0), al1 = exp2f(m1 - mn1);
        m0 = mn0; m1 = mn1;
        l0 *= al0; l1 *= al1;
#pragma unroll
        for (int c = 0; c < 4; c++) {
            o[c][0] *= al0; o[c][1] *= al0;
            o[c][2] *= al1; o[c][3] *= al1;
        }
        float ps0 = 0.f, ps1 = 0.f;
#pragma unroll
        for (int nt = 0; nt < 8; nt++) {
            float p0 = exp2f(s[nt][0] - mn0);
            float p1 = exp2f(s[nt][1] - mn0);
            float p2 = exp2f(s[nt][2] - mn1);
            float p3 = exp2f(s[nt][3] - mn1);
            ps0 += p0 + p1; ps1 += p2 + p3;
            uint2 lo = make_uint2(tf32_of(p0), tf32_of(p1));
            uint2 hi = make_uint2(tf32_of(p2), tf32_of(p3));
            *(uint2*)&Pw[g * 72 + nt * 8 + 2 * t] = lo;
            *(uint2*)&Pw[(g + 8) * 72 + nt * 8 + 2 * t] = hi;
        }
        ps0 += __shfl_xor_sync(0xffffffffu, ps0, 1, 4);
        ps0 += __shfl_xor_sync(0xffffffffu, ps0, 2, 4);
        ps1 += __shfl_xor_sync(0xffffffffu, ps1, 1, 4);
        ps1 += __shfl_xor_sync(0xffffffffu, ps1, 2, 4);
        l0 += ps0; l1 += ps1;
        __syncwarp();

#pragma unroll
        for (int c = 0; c < 8; c++) {
            unsigned pa[4];
            pa[0] = __float_as_uint(Pw[g * 72 + c * 8 + t]);
            pa[1] = __float_as_uint(Pw[(g + 8) * 72 + c * 8 + t]);
            pa[2] = __float_as_uint(Pw[g * 72 + c * 8 + t + 4]);
            pa[3] = __float_as_uint(Pw[(g + 8) * 72 + c * 8 + t + 4]);
#pragma unroll
            for (int nt2 = 0; nt2 < 4; nt2++) {
                unsigned b0 = __float_as_uint(Vs_s[(c * 8 + t) * 41 + nt2 * 8 + g]);
                unsigned b1 = __float_as_uint(Vs_s[(c * 8 + t + 4) * 41 + nt2 * 8 + g]);
                mma_tf32(o[nt2], pa, b0, b1);
            }
        }
        __syncwarp();
    }

    float inv0 = 1.f / l0, inv1 = 1.f / l1;
    float* av = g_av + (size_t)b * 32 * NPIX;
#pragma unroll
    for (int nt2 = 0; nt2 < 4; nt2++) {
        int ch = nt2 * 8 + 2 * t;
        av[(size_t)ch * NPIX + qrow]           = o[nt2][0] * inv0;
        av[(size_t)(ch + 1) * NPIX + qrow]     = o[nt2][1] * inv0;
        av[(size_t)ch * NPIX + qrow + 8]       = o[nt2][2] * inv1;
        av[(size_t)(ch + 1) * NPIX + qrow + 8] = o[nt2][3] * inv1;
    }
}

// ---------------- depthwise 3x3 conv + bias + GELU ----------------
__global__ void dw_kernel(const float* __restrict__ dw_w, const float* __restrict__ dw_b) {
    int idx = blockIdx.x * 256 + threadIdx.x;          // 4*256*4096
    int n = idx & 4095, c = (idx >> 12) & 255;
    int y = n >> 6, x = n & 63;
    const float* hp = g_h1 + (size_t)(idx >> 12) * NPIX;
    const float* w = dw_w + c * 9;
    float a = 0.f;
#pragma unroll
    for (int ky = 0; ky < 3; ky++) {
        int yy = y + ky - 1;
        if (yy < 0 || yy >= 64) continue;
#pragma unroll
        for (int kx = 0; kx < 3; kx++) {
            int xx = x + kx - 1;
            if (xx < 0 || xx >= 64) continue;
            a += hp[yy * 64 + xx] * w[ky * 3 + kx];
        }
    }
    a += dw_b[c];
    g_h2[idx] = a * normcdff(a);
}

// ---------------- host launcher ----------------
extern "C" void kernel_launch(void* const* d_in, const int* in_sizes, int n_in,
                              void* d_out, int out_size) {
    (void)in_sizes; (void)n_in; (void)out_size;
    const float* x       = (const float*)d_in[0];
    const float* skip    = (const float*)d_in[1];
    const float* qkv_w   = (const float*)d_in[2];
    const float* qkv_b   = (const float*)d_in[3];
    const float* proj_w  = (const float*)d_in[4];
    const float* proj_b  = (const float*)d_in[5];
    const float* edge_w  = (const float*)d_in[6];
    const float* thick_w = (const float*)d_in[7];
    const float* thick_b = (const float*)d_in[8];
    const float* off_w   = (const float*)d_in[9];
    const float* off_b   = (const float*)d_in[10];
    const float* deform_w= (const float*)d_in[11];
    const float* deform_b= (const float*)d_in[12];
    const float* ln_g    = (const float*)d_in[13];
    const float* ln_b    = (const float*)d_in[14];
    const float* mlp1_w  = (const float*)d_in[15];
    const float* mlp1_b  = (const float*)d_in[16];
    const float* dw_w    = (const float*)d_in[17];
    const float* dw_b    = (const float*)d_in[18];
    const float* mlp2_w  = (const float*)d_in[19];
    const float* mlp2_b  = (const float*)d_in[20];
    const float* down_w  = (const float*)d_in[21];
    const float* down_b  = (const float*)d_in[22];
    const float* up_w    = (const float*)d_in[23];
    const float* up_b    = (const float*)d_in[24];
    float* out = (float*)d_out;

    float *p_qkv, *p_av, *p_x2, *p_d, *p_e, *p_h, *p_h1, *p_h2, *p_t;
    float *p_qkvWT, *p_projWT, *p_downWT, *p_mlp1WT, *p_mlp2WT, *p_upWT;
    cudaGetSymbolAddress((void**)&p_qkv,    g_qkv);
    cudaGetSymbolAddress((void**)&p_av,     g_av);
    cudaGetSymbolAddress((void**)&p_x2,     g_x2);
    cudaGetSymbolAddress((void**)&p_d,      g_d);
    cudaGetSymbolAddress((void**)&p_e,      g_e);
    cudaGetSymbolAddress((void**)&p_h,      g_h);
    cudaGetSymbolAddress((void**)&p_h1,     g_h1);
    cudaGetSymbolAddress((void**)&p_h2,     g_h2);
    cudaGetSymbolAddress((void**)&p_t,      g_t);
    cudaGetSymbolAddress((void**)&p_qkvWT,  g_qkvWT);
    cudaGetSymbolAddress((void**)&p_projWT, g_projWT);
    cudaGetSymbolAddress((void**)&p_downWT, g_downWT);
    cudaGetSymbolAddress((void**)&p_mlp1WT, g_mlp1WT);
    cudaGetSymbolAddress((void**)&p_mlp2WT, g_mlp2WT);
    cudaGetSymbolAddress((void**)&p_upWT,   g_upWT);

    prep_kernel<<<128, 256>>>(qkv_w, proj_w, down_w, mlp1_w, mlp2_w, up_w, deform_w);
    upsample_kernel<<<dim3(64, 4), 64>>>(skip, thick_w, thick_b);
    edge_kernel<<<4096, 256>>>(edge_w);
    off_kernel<<<256, 512>>>(off_w, off_b);
    deform_kernel<<<256, 128>>>(deform_b);

    // qkv = conv1x1(x) ; flash attention (tf32) ; proj + residual x
    gemm_tf32<<<dim3(128, 2), 256>>>(x, 256, nullptr, 256, p_qkvWT, qkv_b, 96, nullptr, p_qkv, 0);
    flash_kernel<<<dim3(64, 4), 128>>>();
    gemm_tf32<<<dim3(128, 4), 256>>>(p_av, 32, nullptr, 32, p_projWT, proj_b, 256, x, p_x2, 0);

    // down(concat[x2, d]) + LN fused -> mlp1+gelu -> dw+gelu -> mlp2 + e -> up
    gemm_down_ln<<<128, 256>>>(p_x2, p_d, p_downWT, down_b, ln_g, ln_b);
    gemm_tf32<<<dim3(128, 4), 256>>>(p_h, 64, nullptr, 64, p_mlp1WT, mlp1_b, 256, nullptr, p_h1, 1);
    dw_kernel<<<16384, 256>>>(dw_w, dw_b);
    gemm_tf32<<<dim3(128, 1), 256>>>(p_h2, 256, nullptr, 256, p_mlp2WT, mlp2_b, 64, p_e, p_t, 0);
    gemm_tf32<<<dim3(128, 4), 256>>>(p_t, 64, nullptr, 64, p_upWT, up_b, 256, nullptr, out, 0);
}

// round 15
// speedup vs baseline: 1.1810x; 1.1810x over previous
#include <cuda_runtime.h>
#include <math.h>

#define NPIX 4096

// ---------------- f32x2 packed helpers (sm_100+) ----------------
__device__ __forceinline__ unsigned long long pack2(float lo, float hi) {
    unsigned long long r;
    asm("mov.b64 %0, {%1, %2};" : "=l"(r) : "f"(lo), "f"(hi));
    return r;
}
__device__ __forceinline__ float2 unpack2(unsigned long long v) {
    float2 r;
    asm("mov.b64 {%0, %1}, %2;" : "=f"(r.x), "=f"(r.y) : "l"(v));
    return r;
}
__device__ __forceinline__ void fma2(unsigned long long& d, unsigned long long a, unsigned long long b) {
    asm("fma.rn.f32x2 %0, %1, %2, %3;" : "=l"(d) : "l"(a), "l"(b), "l"(d));
}

// ---------------- tf32 mma helpers ----------------
__device__ __forceinline__ unsigned tf32_of(float f) {
    unsigned r;
    asm("cvt.rna.tf32.f32 %0, %1;" : "=r"(r) : "f"(f));
    return r;
}
__device__ __forceinline__ void mma_tf32(float* d, const unsigned* a, unsigned b0, unsigned b1) {
    asm volatile(
        "mma.sync.aligned.m16n8k8.row.col.f32.tf32.tf32.f32 "
        "{%0,%1,%2,%3}, {%4,%5,%6,%7}, {%8,%9}, {%0,%1,%2,%3};"
        : "+f"(d[0]), "+f"(d[1]), "+f"(d[2]), "+f"(d[3])
        : "r"(a[0]), "r"(a[1]), "r"(a[2]), "r"(a[3]), "r"(b0), "r"(b1));
}

// ---------------- scratch (device globals; allocation forbidden) ----------------
__device__ __align__(128) float g_skip_u[4 * NPIX * 64];   // NHWC [b][n][c]
__device__ __align__(128) float g_mean  [4 * NPIX];
__device__ __align__(128) float g_thick [4 * NPIX];
__device__ __align__(128) float g_edge  [4 * NPIX * 64];   // NHWC [b][n][c]
__device__ __align__(128) float g_off   [4 * NPIX * 18];   // NHWC [b][n][18]
__device__ __align__(128) float g_d     [4 * 64 * NPIX];   // NCHW
__device__ __align__(128) float g_qkv   [4 * 96 * NPIX];
__device__ __align__(128) float g_av    [4 * 32 * NPIX];
__device__ __align__(128) float g_x2    [4 * 256 * NPIX];
__device__ __align__(128) float g_e     [4 * 64 * NPIX];
__device__ __align__(128) float g_h     [4 * 64 * NPIX];
__device__ __align__(128) float g_h1    [4 * 256 * NPIX];
__device__ __align__(128) float g_h2    [4 * 256 * NPIX];
__device__ __align__(128) float g_t     [4 * 64 * NPIX];
// transposed weights [IC][OC], pre-rounded to tf32
__device__ __align__(128) float g_qkvWT [256 * 96];
__device__ __align__(128) float g_projWT[32 * 256];
__device__ __align__(128) float g_downWT[320 * 64];
__device__ __align__(128) float g_mlp1WT[64 * 256];
__device__ __align__(128) float g_mlp2WT[256 * 64];
__device__ __align__(128) float g_upWT  [64 * 256];
__device__ __align__(128) float g_dwT   [9 * 64 * 64];   // deform_w as [k][c][o] (fp32)

// ---------------- prep: transpose weights (GEMM weights stored as tf32 bits) ----------------
__global__ void prep_kernel(const float* __restrict__ qkv_w, const float* __restrict__ proj_w,
                            const float* __restrict__ down_w, const float* __restrict__ mlp1_w,
                            const float* __restrict__ mlp2_w, const float* __restrict__ up_w,
                            const float* __restrict__ deform_w) {
    int t0 = blockIdx.x * blockDim.x + threadIdx.x;
    int stride = gridDim.x * blockDim.x;
    for (int i = t0; i < 256 * 96; i += stride) { int ic = i / 96,  oc = i % 96;  g_qkvWT[i]  = __uint_as_float(tf32_of(qkv_w[oc * 256 + ic])); }
    for (int i = t0; i < 32 * 256; i += stride) { int ic = i / 256, oc = i % 256; g_projWT[i] = __uint_as_float(tf32_of(proj_w[oc * 32 + ic])); }
    for (int i = t0; i < 320 * 64; i += stride) { int ic = i / 64,  oc = i % 64;  g_downWT[i] = __uint_as_float(tf32_of(down_w[oc * 320 + ic])); }
    for (int i = t0; i < 64 * 256; i += stride) { int ic = i / 256, oc = i % 256; g_mlp1WT[i] = __uint_as_float(tf32_of(mlp1_w[oc * 64 + ic])); }
    for (int i = t0; i < 256 * 64; i += stride) { int ic = i / 64,  oc = i % 64;  g_mlp2WT[i] = __uint_as_float(tf32_of(mlp2_w[oc * 256 + ic])); }
    for (int i = t0; i < 64 * 256; i += stride) { int ic = i / 256, oc = i % 256; g_upWT[i]   = __uint_as_float(tf32_of(up_w[oc * 64 + ic])); }
    for (int i = t0; i < 9 * 64 * 64; i += stride) {
        int k = i >> 12, c = (i >> 6) & 63, o = i & 63;
        g_dwT[i] = deform_w[(o * 64 + c) * 9 + k];
    }
}

// ---------------- bilinear upsample (half-pixel) + channel mean + thick (NHWC out) ----------------
__global__ void upsample_kernel(const float* __restrict__ skip, const float* __restrict__ thick_w,
                                const float* __restrict__ thick_b) {
    int b = blockIdx.y, y = blockIdx.x, x = threadIdx.x;
    float sy = fminf(fmaxf(0.5f * y - 0.25f, 0.f), 31.f);
    float sx = fminf(fmaxf(0.5f * x - 0.25f, 0.f), 31.f);
    int y0 = (int)sy, x0 = (int)sx;
    int y1 = min(y0 + 1, 31), x1 = min(x0 + 1, 31);
    float wy = sy - (float)y0, wx = sx - (float)x0;
    float w00 = (1.f - wy) * (1.f - wx), w01 = (1.f - wy) * wx;
    float w10 = wy * (1.f - wx),         w11 = wy * wx;
    const float* sp = skip + (size_t)b * 64 * 1024;
    int pix = b * NPIX + y * 64 + x;
    float* up = g_skip_u + (size_t)pix * 64;
    float sum = 0.f, tsum = 0.f;
    for (int c = 0; c < 64; c++) {
        const float* p = sp + c * 1024;
        float v = w00 * p[y0 * 32 + x0] + w01 * p[y0 * 32 + x1]
                + w10 * p[y1 * 32 + x0] + w11 * p[y1 * 32 + x1];
        up[c] = v;
        sum += v;
        tsum += v * thick_w[c];
    }
    g_mean[pix] = sum * (1.f / 64.f);
    g_thick[pix] = 1.f / (1.f + expf(-(tsum + thick_b[0])));
}

// ---------------- edge conv: 3x3, 1 -> 64 ch, zero pad, no bias (NHWC out) ----------------
__global__ void edge_kernel(const float* __restrict__ edge_w) {
    int idx = blockIdx.x * 256 + threadIdx.x;          // 4*4096*64, oc fastest
    int oc = idx & 63, n = (idx >> 6) & 4095, b = idx >> 18;
    int y = n >> 6, x = n & 63;
    const float* mp = g_mean + b * NPIX;
    float a = 0.f;
#pragma unroll
    for (int ky = 0; ky < 3; ky++) {
        int yy = y + ky - 1;
        if (yy < 0 || yy >= 64) continue;
#pragma unroll
        for (int kx = 0; kx < 3; kx++) {
            int xx = x + kx - 1;
            if (xx < 0 || xx >= 64) continue;
            a += mp[yy * 64 + xx] * edge_w[oc * 9 + ky * 3 + kx];
        }
    }
    g_edge[idx] = a;
}

// ---------------- offset conv: 3x3, 64 -> 18, * (1 + 16*thick) ----------------
__global__ __launch_bounds__(512) void off_kernel(const float* __restrict__ off_w,
                                                  const float* __restrict__ off_b) {
    __shared__ float pool[64 * 9 * 18];                // ws, then reused as red[4*128*18]
    float* ws = pool;
    for (int i = threadIdx.x; i < 64 * 9 * 18; i += 512) {
        int o = i % 18, ck = i / 18;
        ws[i] = off_w[o * 576 + ck];                   // [c][k][o]
    }
    __syncthreads();
    int pl = threadIdx.x & 127, g = threadIdx.x >> 7;
    int pix = blockIdx.x * 128 + pl;
    int b = pix >> 12, n = pix & 4095;
    int y = n >> 6, x = n & 63;
    unsigned long long acc[9];
#pragma unroll
    for (int o = 0; o < 9; o++) acc[o] = 0ull;
    const float* ep = g_edge + (size_t)b * NPIX * 64;
#pragma unroll
    for (int ky = 0; ky < 3; ky++) {
        int yy = y + ky - 1;
        if (yy < 0 || yy >= 64) continue;
#pragma unroll
        for (int kx = 0; kx < 3; kx++) {
            int xx = x + kx - 1;
            if (xx < 0 || xx >= 64) continue;
            int k = ky * 3 + kx;
            const float4* col = (const float4*)(ep + (size_t)(yy * 64 + xx) * 64 + g * 16);
#pragma unroll
            for (int c4 = 0; c4 < 4; c4++) {
                float4 v4 = col[c4];
#pragma unroll
                for (int cc = 0; cc < 4; cc++) {
                    float v = (cc == 0) ? v4.x : (cc == 1) ? v4.y : (cc == 2) ? v4.z : v4.w;
                    unsigned long long vd = pack2(v, v);
                    const unsigned long long* wr =
                        (const unsigned long long*)&ws[((g * 16 + c4 * 4 + cc) * 9 + k) * 18];
#pragma unroll
                    for (int o = 0; o < 9; o++) fma2(acc[o], vd, wr[o]);
                }
            }
        }
    }
    __syncthreads();                                   // done with ws reads
    float* red = pool;                                 // [4][128][18]
#pragma unroll
    for (int o = 0; o < 9; o++)
        *(float2*)&red[((g * 128 + pl) * 18) + 2 * o] = unpack2(acc[o]);
    __syncthreads();
    for (int i = threadIdx.x; i < 128 * 18; i += 512) {
        int p2 = i / 18, o = i % 18;
        float s = red[(0 * 128 + p2) * 18 + o] + red[(1 * 128 + p2) * 18 + o]
                + red[(2 * 128 + p2) * 18 + o] + red[(3 * 128 + p2) * 18 + o];
        int gp = blockIdx.x * 128 + p2;
        float tscale = 1.f + 16.f * g_thick[gp];
        g_off[(size_t)gp * 18 + o] = (s + off_b[o]) * tscale;
    }
}

// ---------------- deformable conv 3x3 (DCNv1) + bias + edge ----------------
__global__ __launch_bounds__(64) void deform_kernel(const float* __restrict__ deform_b) {
    __shared__ float ws[4096];                         // [c][o] for current tap
    int pix = blockIdx.x * 64 + threadIdx.x;           // 16384
    int b = pix >> 12, n = pix & 4095;
    int y = n >> 6, x = n & 63;
    unsigned long long acc[32];
#pragma unroll
    for (int o = 0; o < 32; o++) acc[o] = 0ull;
    const float* su = g_skip_u + (size_t)b * NPIX * 64;
    const float* offp = g_off + (size_t)pix * 18;
    for (int k = 0; k < 9; k++) {
        __syncthreads();
        for (int i = threadIdx.x * 4; i < 4096; i += 64 * 4)
            *(float4*)&ws[i] = *(const float4*)&g_dwT[k * 4096 + i];
        __syncthreads();
        float py = (float)(y + k / 3 - 1) + offp[2 * k];
        float px = (float)(x + k % 3 - 1) + offp[2 * k + 1];
        float y0f = floorf(py), x0f = floorf(px);
        float wy = py - y0f, wx = px - x0f;
        int y0 = (int)y0f, x0 = (int)x0f;
        int y1 = y0 + 1, x1 = x0 + 1;
        bool vy0 = (y0 >= 0 && y0 < 64), vy1 = (y1 >= 0 && y1 < 64);
        bool vx0 = (x0 >= 0 && x0 < 64), vx1 = (x1 >= 0 && x1 < 64);
        float w00 = (vy0 && vx0) ? (1.f - wy) * (1.f - wx) : 0.f;
        float w01 = (vy0 && vx1) ? (1.f - wy) * wx : 0.f;
        float w10 = (vy1 && vx0) ? wy * (1.f - wx) : 0.f;
        float w11 = (vy1 && vx1) ? wy * wx : 0.f;
        int yc0 = min(max(y0, 0), 63), yc1 = min(max(y1, 0), 63);
        int xc0 = min(max(x0, 0), 63), xc1 = min(max(x1, 0), 63);
        const float4* p00 = (const float4*)(su + (size_t)(yc0 * 64 + xc0) * 64);
        const float4* p01 = (const float4*)(su + (size_t)(yc0 * 64 + xc1) * 64);
        const float4* p10 = (const float4*)(su + (size_t)(yc1 * 64 + xc0) * 64);
        const float4* p11 = (const float4*)(su + (size_t)(yc1 * 64 + xc1) * 64);
        for (int c4 = 0; c4 < 16; c4++) {
            float4 a0 = p00[c4], a1 = p01[c4], a2 = p10[c4], a3 = p11[c4];
            float4 val4;
            val4.x = w00 * a0.x + w01 * a1.x + w10 * a2.x + w11 * a3.x;
            val4.y = w00 * a0.y + w01 * a1.y + w10 * a2.y + w11 * a3.y;
            val4.z = w00 * a0.z + w01 * a1.z + w10 * a2.z + w11 * a3.z;
            val4.w = w00 * a0.w + w01 * a1.w + w10 * a2.w + w11 * a3.w;
#pragma unroll
            for (int cc = 0; cc < 4; cc++) {
                float v = (cc == 0) ? val4.x : (cc == 1) ? val4.y : (cc == 2) ? val4.z : val4.w;
                unsigned long long vd = pack2(v, v);
                const unsigned long long* wr = (const unsigned long long*)&ws[(c4 * 4 + cc) * 64];
#pragma unroll
                for (int o = 0; o < 32; o++) fma2(acc[o], vd, wr[o]);
            }
        }
    }
    const float* ep = g_edge + (size_t)pix * 64;
    float* dp = g_d + (size_t)b * 64 * NPIX + n;
#pragma unroll
    for (int o2 = 0; o2 < 32; o2++) {
        float2 a2 = unpack2(acc[o2]);
        dp[(size_t)(2 * o2 + 0) * NPIX] = a2.x + deform_b[2 * o2 + 0] + ep[2 * o2 + 0];
        dp[(size_t)(2 * o2 + 1) * NPIX] = a2.y + deform_b[2 * o2 + 1] + ep[2 * o2 + 1];
    }
}

// ---------------- 1x1-conv GEMM on tensor cores (tf32 mma.sync) ----------------
__global__ __launch_bounds__(256) void gemm_tf32(const float* __restrict__ inA, int icA,
                                                 const float* __restrict__ inB, int IC,
                                                 const float* __restrict__ WT,
                                                 const float* __restrict__ bias, int OC,
                                                 const float* __restrict__ res,
                                                 float* __restrict__ out, int act) {
    __shared__ float Bs[16][136];
    __shared__ float Ws[16][72];
    int tid = threadIdx.x;
    int lane = tid & 31, w = tid >> 5;
    int g = lane >> 2, t = lane & 3;
    int wm = w >> 2, wn = w & 3;
    int n0 = blockIdx.x * 128;
    int oc0 = blockIdx.y * 64;
    int lb = n0 >> 12, ln = n0 & 4095;
    int icB = IC - icA;

    float acc[2][4][4];
#pragma unroll
    for (int mt = 0; mt < 2; mt++)
#pragma unroll
        for (int nt = 0; nt < 4; nt++)
#pragma unroll
            for (int j = 0; j < 4; j++) acc[mt][nt][j] = 0.f;

    int brow = tid >> 4, bcol = (tid & 15) * 8;
    int wrow = tid >> 4, wcol = (tid & 15) * 4;

    for (int k0 = 0; k0 < IC; k0 += 16) {
        __syncthreads();
        {
            int ic = k0 + brow;
            const float* src;
            if (ic < icA) src = inA + ((size_t)lb * icA + ic) * NPIX + ln + bcol;
            else          src = inB + ((size_t)lb * icB + (ic - icA)) * NPIX + ln + bcol;
            float4 v0 = *(const float4*)src;
            float4 v1 = *(const float4*)(src + 4);
            float4 s0, s1;
            s0.x = __uint_as_float(tf32_of(v0.x)); s0.y = __uint_as_float(tf32_of(v0.y));
            s0.z = __uint_as_float(tf32_of(v0.z)); s0.w = __uint_as_float(tf32_of(v0.w));
            s1.x = __uint_as_float(tf32_of(v1.x)); s1.y = __uint_as_float(tf32_of(v1.y));
            s1.z = __uint_as_float(tf32_of(v1.z)); s1.w = __uint_as_float(tf32_of(v1.w));
            *(float4*)&Bs[brow][bcol] = s0;
            *(float4*)&Bs[brow][bcol + 4] = s1;
        }
        {
            const float* wsrc = WT + (size_t)(k0 + wrow) * OC + oc0 + wcol;
            float4 wv;
            if (oc0 + wcol + 3 < OC) {
                wv = *(const float4*)wsrc;
            } else {
                wv.x = (oc0 + wcol + 0 < OC) ? wsrc[0] : 0.f;
                wv.y = (oc0 + wcol + 1 < OC) ? wsrc[1] : 0.f;
                wv.z = (oc0 + wcol + 2 < OC) ? wsrc[2] : 0.f;
                wv.w = (oc0 + wcol + 3 < OC) ? wsrc[3] : 0.f;
            }
            *(float4*)&Ws[wrow][wcol] = wv;   // weights pre-rounded to tf32 in prep
        }
        __syncthreads();
#pragma unroll
        for (int ks = 0; ks < 2; ks++) {
            int kb = ks * 8;
            unsigned af[2][4];
#pragma unroll
            for (int mt = 0; mt < 2; mt++) {
                int row = wm * 32 + mt * 16;
                af[mt][0] = __float_as_uint(Ws[kb + t][row + g]);
                af[mt][1] = __float_as_uint(Ws[kb + t][row + g + 8]);
                af[mt][2] = __float_as_uint(Ws[kb + t + 4][row + g]);
                af[mt][3] = __float_as_uint(Ws[kb + t + 4][row + g + 8]);
            }
#pragma unroll
            for (int nt = 0; nt < 4; nt++) {
                int col = wn * 32 + nt * 8 + g;
                unsigned b0 = __float_as_uint(Bs[kb + t][col]);
                unsigned b1 = __float_as_uint(Bs[kb + t + 4][col]);
                mma_tf32(acc[0][nt], af[0], b0, b1);
                mma_tf32(acc[1][nt], af[1], b0, b1);
            }
        }
    }
#pragma unroll
    for (int mt = 0; mt < 2; mt++) {
#pragma unroll
        for (int nt = 0; nt < 4; nt++) {
            int col = ln + wn * 32 + nt * 8 + 2 * t;
#pragma unroll
            for (int r = 0; r < 2; r++) {
                int oc = oc0 + wm * 32 + mt * 16 + g + r * 8;
                if (oc < OC) {
                    float v0 = acc[mt][nt][r * 2 + 0] + bias[oc];
                    float v1 = acc[mt][nt][r * 2 + 1] + bias[oc];
                    if (act) { v0 = v0 * normcdff(v0); v1 = v1 * normcdff(v1); }
                    size_t oi = ((size_t)lb * OC + oc) * NPIX + col;
                    if (res) { v0 += res[oi]; v1 += res[oi + 1]; }
                    *(float2*)&out[oi] = make_float2(v0, v1);
                }
            }
        }
    }
}

// ---------------- flash attention (tf32 mma.sync): N=4096, d=32 per batch ----------------
__global__ __launch_bounds__(128) void flash_kernel() {
    __shared__ float Kt_s[32 * 72];        // [ch][key]
    __shared__ float Vs_s[64 * 41];        // [key][ch]
    __shared__ float Ps_s[4 * 16 * 72];    // per-warp P tile
    int b = blockIdx.y;
    int q0 = blockIdx.x * 64;
    int tid = threadIdx.x;
    int w = tid >> 5, lane = tid & 31;
    int g = lane >> 2, t = lane & 3;
    const float* qkv = g_qkv + (size_t)b * 96 * NPIX;
    const float QSCALE = 1.4426950408889634f * 0.17677669529663687f;
    int qrow = q0 + w * 16 + g;

    unsigned qa[4][4];
#pragma unroll
    for (int kc = 0; kc < 4; kc++) {
        qa[kc][0] = tf32_of(qkv[(size_t)(kc * 8 + t) * NPIX + qrow] * QSCALE);
        qa[kc][1] = tf32_of(qkv[(size_t)(kc * 8 + t) * NPIX + qrow + 8] * QSCALE);
        qa[kc][2] = tf32_of(qkv[(size_t)(kc * 8 + t + 4) * NPIX + qrow] * QSCALE);
        qa[kc][3] = tf32_of(qkv[(size_t)(kc * 8 + t + 4) * NPIX + qrow + 8] * QSCALE);
    }

    float m0 = -INFINITY, m1 = -INFINITY, l0 = 0.f, l1 = 0.f;
    float o[4][4];
#pragma unroll
    for (int i = 0; i < 4; i++)
#pragma unroll
        for (int j = 0; j < 4; j++) o[i][j] = 0.f;
    float* Pw = Ps_s + w * 16 * 72;

    for (int kt = 0; kt < 64; kt++) {
        int k0 = kt * 64;
        __syncthreads();
        for (int i = tid; i < 2048; i += 128) {
            int ch = i >> 6, key = i & 63;
            Kt_s[ch * 72 + key] = __uint_as_float(tf32_of(qkv[(size_t)(32 + ch) * NPIX + k0 + key]));
            Vs_s[key * 41 + ch] = __uint_as_float(tf32_of(qkv[(size_t)(64 + ch) * NPIX + k0 + key]));
        }
        __syncthreads();

        float s[8][4];
#pragma unroll
        for (int nt = 0; nt < 8; nt++)
#pragma unroll
            for (int j = 0; j < 4; j++) s[nt][j] = 0.f;
#pragma unroll
        for (int nt = 0; nt < 8; nt++) {
#pragma unroll
            for (int kc = 0; kc < 4; kc++) {
                unsigned b0 = __float_as_uint(Kt_s[(kc * 8 + t) * 72 + nt * 8 + g]);
                unsigned b1 = __float_as_uint(Kt_s[(kc * 8 + t + 4) * 72 + nt * 8 + g]);
                mma_tf32(s[nt], qa[kc], b0, b1);
            }
        }

        float pm0 = -INFINITY, pm1 = -INFINITY;
#pragma unroll
        for (int nt = 0; nt < 8; nt++) {
            pm0 = fmaxf(pm0, fmaxf(s[nt][0], s[nt][1]));
            pm1 = fmaxf(pm1, fmaxf(s[nt][2], s[nt][3]));
        }
        pm0 = fmaxf(pm0, __shfl_xor_sync(0xffffffffu, pm0, 1, 4));
        pm0 = fmaxf(pm0, __shfl_xor_sync(0xffffffffu, pm0, 2, 4));
        pm1 = fmaxf(pm1, __shfl_xor_sync(0xffffffffu, pm1, 1, 4));
        pm1 = fmaxf(pm1, __shfl_xor_sync(0xffffffffu, pm1, 2, 4));
        float mn0 = fmaxf(m0, pm0), mn1 = fmaxf(m1, pm1);
        float al0 = exp2f(m0 - mn0), al1 = exp2f(m1 - mn1);
        m0 = mn0; m1 = mn1;
        l0 *= al0; l1 *= al1;
#pragma unroll
        for (int c = 0; c < 4; c++) {
            o[c][0] *= al0; o[c][1] *= al0;
            o[c][2] *= al1; o[c][3] *= al1;
        }
        float ps0 = 0.f, ps1 = 0.f;
#pragma unroll
        for (int nt = 0; nt < 8; nt++) {
            float p0 = exp2f(s[nt][0] - mn0);
            float p1 = exp2f(s[nt][1] - mn0);
            float p2 = exp2f(s[nt][2] - mn1);
            float p3 = exp2f(s[nt][3] - mn1);
            ps0 += p0 + p1; ps1 += p2 + p3;
            uint2 lo = make_uint2(tf32_of(p0), tf32_of(p1));
            uint2 hi = make_uint2(tf32_of(p2), tf32_of(p3));
            *(uint2*)&Pw[g * 72 + nt * 8 + 2 * t] = lo;
            *(uint2*)&Pw[(g + 8) * 72 + nt * 8 + 2 * t] = hi;
        }
        ps0 += __shfl_xor_sync(0xffffffffu, ps0, 1, 4);
        ps0 += __shfl_xor_sync(0xffffffffu, ps0, 2, 4);
        ps1 += __shfl_xor_sync(0xffffffffu, ps1, 1, 4);
        ps1 += __shfl_xor_sync(0xffffffffu, ps1, 2, 4);
        l0 += ps0; l1 += ps1;
        __syncwarp();

#pragma unroll
        for (int c = 0; c < 8; c++) {
            unsigned pa[4];
            pa[0] = __float_as_uint(Pw[g * 72 + c * 8 + t]);
            pa[1] = __float_as_uint(Pw[(g + 8) * 72 + c * 8 + t]);
            pa[2] = __float_as_uint(Pw[g * 72 + c * 8 + t + 4]);
            pa[3] = __float_as_uint(Pw[(g + 8) * 72 + c * 8 + t + 4]);
#pragma unroll
            for (int nt2 = 0; nt2 < 4; nt2++) {
                unsigned b0 = __float_as_uint(Vs_s[(c * 8 + t) * 41 + nt2 * 8 + g]);
                unsigned b1 = __float_as_uint(Vs_s[(c * 8 + t + 4) * 41 + nt2 * 8 + g]);
                mma_tf32(o[nt2], pa, b0, b1);
            }
        }
        __syncwarp();
    }

    float inv0 = 1.f / l0, inv1 = 1.f / l1;
    float* av = g_av + (size_t)b * 32 * NPIX;
#pragma unroll
    for (int nt2 = 0; nt2 < 4; nt2++) {
        int ch = nt2 * 8 + 2 * t;
        av[(size_t)ch * NPIX + qrow]           = o[nt2][0] * inv0;
        av[(size_t)(ch + 1) * NPIX + qrow]     = o[nt2][1] * inv0;
        av[(size_t)ch * NPIX + qrow + 8]       = o[nt2][2] * inv1;
        av[(size_t)(ch + 1) * NPIX + qrow + 8] = o[nt2][3] * inv1;
    }
}

// ---------------- layernorm over 64 channels per pixel ----------------
__global__ void ln_kernel(const float* __restrict__ ln_g, const float* __restrict__ ln_b) {
    int p = blockIdx.x * 256 + threadIdx.x;
    int b = p >> 12, n = p & 4095;
    const float* ep = g_e + (size_t)b * 64 * NPIX + n;
    float v[64], mu = 0.f;
#pragma unroll
    for (int c = 0; c < 64; c++) { v[c] = ep[(size_t)c * NPIX]; mu += v[c]; }
    mu *= (1.f / 64.f);
    float var = 0.f;
#pragma unroll
    for (int c = 0; c < 64; c++) { float d = v[c] - mu; var += d * d; }
    var *= (1.f / 64.f);
    float inv = rsqrtf(var + 1e-5f);
    float* hp = g_h + (size_t)b * 64 * NPIX + n;
#pragma unroll
    for (int c = 0; c < 64; c++) hp[(size_t)c * NPIX] = (v[c] - mu) * inv * ln_g[c] + ln_b[c];
}

// ---------------- depthwise 3x3 conv + bias + GELU ----------------
__global__ void dw_kernel(const float* __restrict__ dw_w, const float* __restrict__ dw_b) {
    int idx = blockIdx.x * 256 + threadIdx.x;          // 4*256*4096
    int n = idx & 4095, c = (idx >> 12) & 255;
    int y = n >> 6, x = n & 63;
    const float* hp = g_h1 + (size_t)(idx >> 12) * NPIX;
    const float* w = dw_w + c * 9;
    float a = 0.f;
#pragma unroll
    for (int ky = 0; ky < 3; ky++) {
        int yy = y + ky - 1;
        if (yy < 0 || yy >= 64) continue;
#pragma unroll
        for (int kx = 0; kx < 3; kx++) {
            int xx = x + kx - 1;
            if (xx < 0 || xx >= 64) continue;
            a += hp[yy * 64 + xx] * w[ky * 3 + kx];
        }
    }
    a += dw_b[c];
    g_h2[idx] = a * normcdff(a);
}

// ---------------- host launcher ----------------
extern "C" void kernel_launch(void* const* d_in, const int* in_sizes, int n_in,
                              void* d_out, int out_size) {
    (void)in_sizes; (void)n_in; (void)out_size;
    const float* x       = (const float*)d_in[0];
    const float* skip    = (const float*)d_in[1];
    const float* qkv_w   = (const float*)d_in[2];
    const float* qkv_b   = (const float*)d_in[3];
    const float* proj_w  = (const float*)d_in[4];
    const float* proj_b  = (const float*)d_in[5];
    const float* edge_w  = (const float*)d_in[6];
    const float* thick_w = (const float*)d_in[7];
    const float* thick_b = (const float*)d_in[8];
    const float* off_w   = (const float*)d_in[9];
    const float* off_b   = (const float*)d_in[10];
    const float* deform_w= (const float*)d_in[11];
    const float* deform_b= (const float*)d_in[12];
    const float* ln_g    = (const float*)d_in[13];
    const float* ln_b    = (const float*)d_in[14];
    const float* mlp1_w  = (const float*)d_in[15];
    const float* mlp1_b  = (const float*)d_in[16];
    const float* dw_w    = (const float*)d_in[17];
    const float* dw_b    = (const float*)d_in[18];
    const float* mlp2_w  = (const float*)d_in[19];
    const float* mlp2_b  = (const float*)d_in[20];
    const float* down_w  = (const float*)d_in[21];
    const float* down_b  = (const float*)d_in[22];
    const float* up_w    = (const float*)d_in[23];
    const float* up_b    = (const float*)d_in[24];
    float* out = (float*)d_out;

    float *p_qkv, *p_av, *p_x2, *p_d, *p_e, *p_h, *p_h1, *p_h2, *p_t;
    float *p_qkvWT, *p_projWT, *p_downWT, *p_mlp1WT, *p_mlp2WT, *p_upWT;
    cudaGetSymbolAddress((void**)&p_qkv,    g_qkv);
    cudaGetSymbolAddress((void**)&p_av,     g_av);
    cudaGetSymbolAddress((void**)&p_x2,     g_x2);
    cudaGetSymbolAddress((void**)&p_d,      g_d);
    cudaGetSymbolAddress((void**)&p_e,      g_e);
    cudaGetSymbolAddress((void**)&p_h,      g_h);
    cudaGetSymbolAddress((void**)&p_h1,     g_h1);
    cudaGetSymbolAddress((void**)&p_h2,     g_h2);
    cudaGetSymbolAddress((void**)&p_t,      g_t);
    cudaGetSymbolAddress((void**)&p_qkvWT,  g_qkvWT);
    cudaGetSymbolAddress((void**)&p_projWT, g_projWT);
    cudaGetSymbolAddress((void**)&p_downWT, g_downWT);
    cudaGetSymbolAddress((void**)&p_mlp1WT, g_mlp1WT);
    cudaGetSymbolAddress((void**)&p_mlp2WT, g_mlp2WT);
    cudaGetSymbolAddress((void**)&p_upWT,   g_upWT);

    // one-time stream/event creation (host resources, not device memory).
    // If creation fails for any reason, fall back to fully-serial launches.
    static cudaStream_t s1 = nullptr;
    static cudaEvent_t ev_fork = nullptr, ev_join = nullptr;
    static int use_streams = -1;
    if (use_streams < 0) {
        cudaError_t e1 = cudaStreamCreateWithFlags(&s1, cudaStreamNonBlocking);
        cudaError_t e2 = cudaEventCreateWithFlags(&ev_fork, cudaEventDisableTiming);
        cudaError_t e3 = cudaEventCreateWithFlags(&ev_join, cudaEventDisableTiming);
        use_streams = (e1 == cudaSuccess && e2 == cudaSuccess && e3 == cudaSuccess) ? 1 : 0;
    }

    prep_kernel<<<128, 256>>>(qkv_w, proj_w, down_w, mlp1_w, mlp2_w, up_w, deform_w);

    if (use_streams) {
        // fork: skip path on s1, attention path on default stream
        cudaEventRecord(ev_fork, 0);
        cudaStreamWaitEvent(s1, ev_fork, 0);

        upsample_kernel<<<dim3(64, 4), 64, 0, s1>>>(skip, thick_w, thick_b);
        edge_kernel<<<4096, 256, 0, s1>>>(edge_w);
        off_kernel<<<128, 512, 0, s1>>>(off_w, off_b);
        deform_kernel<<<256, 64, 0, s1>>>(deform_b);
        cudaEventRecord(ev_join, s1);

        gemm_tf32<<<dim3(128, 2), 256>>>(x, 256, nullptr, 256, p_qkvWT, qkv_b, 96, nullptr, p_qkv, 0);
        flash_kernel<<<dim3(64, 4), 128>>>();
        gemm_tf32<<<dim3(128, 4), 256>>>(p_av, 32, nullptr, 32, p_projWT, proj_b, 256, x, p_x2, 0);

        // join: down needs both x2 (default stream) and d (s1)
        cudaStreamWaitEvent(0, ev_join, 0);
    } else {
        upsample_kernel<<<dim3(64, 4), 64>>>(skip, thick_w, thick_b);
        edge_kernel<<<4096, 256>>>(edge_w);
        off_kernel<<<128, 512>>>(off_w, off_b);
        deform_kernel<<<256, 64>>>(deform_b);
        gemm_tf32<<<dim3(128, 2), 256>>>(x, 256, nullptr, 256, p_qkvWT, qkv_b, 96, nullptr, p_qkv, 0);
        flash_kernel<<<dim3(64, 4), 128>>>();
        gemm_tf32<<<dim3(128, 4), 256>>>(p_av, 32, nullptr, 32, p_projWT, proj_b, 256, x, p_x2, 0);
    }

    gemm_tf32<<<dim3(128, 1), 256>>>(p_x2, 256, p_d, 320, p_downWT, down_b, 64, nullptr, p_e, 0);
    ln_kernel<<<64, 256>>>(ln_g, ln_b);
    gemm_tf32<<<dim3(128, 4), 256>>>(p_h, 64, nullptr, 64, p_mlp1WT, mlp1_b, 256, nullptr, p_h1, 1);
    dw_kernel<<<16384, 256>>>(dw_w, dw_b);
    gemm_tf32<<<dim3(128, 1), 256>>>(p_h2, 256, nullptr, 256, p_mlp2WT, mlp2_b, 64, p_e, p_t, 0);
    gemm_tf32<<<dim3(128, 4), 256>>>(p_t, 64, nullptr, 64, p_upWT, up_b, 256, nullptr, out, 0);
}

// round 16
// speedup vs baseline: 1.2270x; 1.0389x over previous
#include <cuda_runtime.h>
#include <math.h>

#define NPIX 4096

// ---------------- f32x2 packed helpers (sm_100+) ----------------
__device__ __forceinline__ unsigned long long pack2(float lo, float hi) {
    unsigned long long r;
    asm("mov.b64 %0, {%1, %2};" : "=l"(r) : "f"(lo), "f"(hi));
    return r;
}
__device__ __forceinline__ float2 unpack2(unsigned long long v) {
    float2 r;
    asm("mov.b64 {%0, %1}, %2;" : "=f"(r.x), "=f"(r.y) : "l"(v));
    return r;
}
__device__ __forceinline__ void fma2(unsigned long long& d, unsigned long long a, unsigned long long b) {
    asm("fma.rn.f32x2 %0, %1, %2, %3;" : "=l"(d) : "l"(a), "l"(b), "l"(d));
}

// ---------------- tf32 mma helpers ----------------
__device__ __forceinline__ unsigned tf32_of(float f) {
    unsigned r;
    asm("cvt.rna.tf32.f32 %0, %1;" : "=r"(r) : "f"(f));
    return r;
}
__device__ __forceinline__ void mma_tf32(float* d, const unsigned* a, unsigned b0, unsigned b1) {
    asm volatile(
        "mma.sync.aligned.m16n8k8.row.col.f32.tf32.tf32.f32 "
        "{%0,%1,%2,%3}, {%4,%5,%6,%7}, {%8,%9}, {%0,%1,%2,%3};"
        : "+f"(d[0]), "+f"(d[1]), "+f"(d[2]), "+f"(d[3])
        : "r"(a[0]), "r"(a[1]), "r"(a[2]), "r"(a[3]), "r"(b0), "r"(b1));
}

// ---------------- scratch (device globals; allocation forbidden) ----------------
__device__ __align__(128) float g_skip_u[4 * NPIX * 64];   // NHWC [b][n][c]
__device__ __align__(128) float g_mean  [4 * NPIX];
__device__ __align__(128) float g_thick [4 * NPIX];
__device__ __align__(128) float g_edge  [4 * NPIX * 64];   // NHWC [b][n][c]
__device__ __align__(128) float g_off   [4 * NPIX * 18];   // NHWC [b][n][18]
__device__ __align__(128) float g_d     [4 * 64 * NPIX];   // NCHW
__device__ __align__(128) float g_qkv   [4 * 96 * NPIX];
__device__ __align__(128) float g_av    [4 * 32 * NPIX];
__device__ __align__(128) float g_x2    [4 * 256 * NPIX];
__device__ __align__(128) float g_e     [4 * 64 * NPIX];
__device__ __align__(128) float g_h     [4 * 64 * NPIX];
__device__ __align__(128) float g_h1    [4 * 256 * NPIX];
__device__ __align__(128) float g_h2    [4 * 256 * NPIX];
__device__ __align__(128) float g_t     [4 * 64 * NPIX];
// transposed weights [IC][OC], pre-rounded to tf32
__device__ __align__(128) float g_qkvWT [256 * 96];
__device__ __align__(128) float g_projWT[32 * 256];
__device__ __align__(128) float g_downWT[320 * 64];
__device__ __align__(128) float g_mlp1WT[64 * 256];
__device__ __align__(128) float g_mlp2WT[256 * 64];
__device__ __align__(128) float g_upWT  [64 * 256];
__device__ __align__(128) float g_dwT   [9 * 64 * 64];   // deform_w as [k][c][o] (fp32)

// ---------------- prep: transpose weights (GEMM weights stored as tf32 bits) ----------------
__global__ void prep_kernel(const float* __restrict__ qkv_w, const float* __restrict__ proj_w,
                            const float* __restrict__ down_w, const float* __restrict__ mlp1_w,
                            const float* __restrict__ mlp2_w, const float* __restrict__ up_w,
                            const float* __restrict__ deform_w) {
    int t0 = blockIdx.x * blockDim.x + threadIdx.x;
    int stride = gridDim.x * blockDim.x;
    for (int i = t0; i < 256 * 96; i += stride) { int ic = i / 96,  oc = i % 96;  g_qkvWT[i]  = __uint_as_float(tf32_of(qkv_w[oc * 256 + ic])); }
    for (int i = t0; i < 32 * 256; i += stride) { int ic = i / 256, oc = i % 256; g_projWT[i] = __uint_as_float(tf32_of(proj_w[oc * 32 + ic])); }
    for (int i = t0; i < 320 * 64; i += stride) { int ic = i / 64,  oc = i % 64;  g_downWT[i] = __uint_as_float(tf32_of(down_w[oc * 320 + ic])); }
    for (int i = t0; i < 64 * 256; i += stride) { int ic = i / 256, oc = i % 256; g_mlp1WT[i] = __uint_as_float(tf32_of(mlp1_w[oc * 64 + ic])); }
    for (int i = t0; i < 256 * 64; i += stride) { int ic = i / 64,  oc = i % 64;  g_mlp2WT[i] = __uint_as_float(tf32_of(mlp2_w[oc * 256 + ic])); }
    for (int i = t0; i < 64 * 256; i += stride) { int ic = i / 256, oc = i % 256; g_upWT[i]   = __uint_as_float(tf32_of(up_w[oc * 64 + ic])); }
    for (int i = t0; i < 9 * 64 * 64; i += stride) {
        int k = i >> 12, c = (i >> 6) & 63, o = i & 63;
        g_dwT[i] = deform_w[(o * 64 + c) * 9 + k];
    }
}

// ---------------- bilinear upsample (half-pixel) + channel mean + thick (NHWC out) ----------------
__global__ void upsample_kernel(const float* __restrict__ skip, const float* __restrict__ thick_w,
                                const float* __restrict__ thick_b) {
    int b = blockIdx.y, y = blockIdx.x, x = threadIdx.x;
    float sy = fminf(fmaxf(0.5f * y - 0.25f, 0.f), 31.f);
    float sx = fminf(fmaxf(0.5f * x - 0.25f, 0.f), 31.f);
    int y0 = (int)sy, x0 = (int)sx;
    int y1 = min(y0 + 1, 31), x1 = min(x0 + 1, 31);
    float wy = sy - (float)y0, wx = sx - (float)x0;
    float w00 = (1.f - wy) * (1.f - wx), w01 = (1.f - wy) * wx;
    float w10 = wy * (1.f - wx),         w11 = wy * wx;
    const float* sp = skip + (size_t)b * 64 * 1024;
    int pix = b * NPIX + y * 64 + x;
    float* up = g_skip_u + (size_t)pix * 64;
    float sum = 0.f, tsum = 0.f;
    for (int c = 0; c < 64; c++) {
        const float* p = sp + c * 1024;
        float v = w00 * p[y0 * 32 + x0] + w01 * p[y0 * 32 + x1]
                + w10 * p[y1 * 32 + x0] + w11 * p[y1 * 32 + x1];
        up[c] = v;
        sum += v;
        tsum += v * thick_w[c];
    }
    g_mean[pix] = sum * (1.f / 64.f);
    g_thick[pix] = 1.f / (1.f + expf(-(tsum + thick_b[0])));
}

// ---------------- edge conv: 3x3, 1 -> 64 ch, zero pad, no bias (NHWC out) ----------------
__global__ void edge_kernel(const float* __restrict__ edge_w) {
    int idx = blockIdx.x * 256 + threadIdx.x;          // 4*4096*64, oc fastest
    int oc = idx & 63, n = (idx >> 6) & 4095, b = idx >> 18;
    int y = n >> 6, x = n & 63;
    const float* mp = g_mean + b * NPIX;
    float a = 0.f;
#pragma unroll
    for (int ky = 0; ky < 3; ky++) {
        int yy = y + ky - 1;
        if (yy < 0 || yy >= 64) continue;
#pragma unroll
        for (int kx = 0; kx < 3; kx++) {
            int xx = x + kx - 1;
            if (xx < 0 || xx >= 64) continue;
            a += mp[yy * 64 + xx] * edge_w[oc * 9 + ky * 3 + kx];
        }
    }
    g_edge[idx] = a;
}

// ---------------- offset conv: 3x3, 64 -> 18, * (1 + 16*thick) ----------------
__global__ __launch_bounds__(512) void off_kernel(const float* __restrict__ off_w,
                                                  const float* __restrict__ off_b) {
    __shared__ float pool[64 * 9 * 18];                // ws, then reused as red[4*128*18]
    float* ws = pool;
    for (int i = threadIdx.x; i < 64 * 9 * 18; i += 512) {
        int o = i % 18, ck = i / 18;
        ws[i] = off_w[o * 576 + ck];                   // [c][k][o]
    }
    __syncthreads();
    int pl = threadIdx.x & 127, g = threadIdx.x >> 7;
    int pix = blockIdx.x * 128 + pl;
    int b = pix >> 12, n = pix & 4095;
    int y = n >> 6, x = n & 63;
    unsigned long long acc[9];
#pragma unroll
    for (int o = 0; o < 9; o++) acc[o] = 0ull;
    const float* ep = g_edge + (size_t)b * NPIX * 64;
#pragma unroll
    for (int ky = 0; ky < 3; ky++) {
        int yy = y + ky - 1;
        if (yy < 0 || yy >= 64) continue;
#pragma unroll
        for (int kx = 0; kx < 3; kx++) {
            int xx = x + kx - 1;
            if (xx < 0 || xx >= 64) continue;
            int k = ky * 3 + kx;
            const float4* col = (const float4*)(ep + (size_t)(yy * 64 + xx) * 64 + g * 16);
#pragma unroll
            for (int c4 = 0; c4 < 4; c4++) {
                float4 v4 = col[c4];
#pragma unroll
                for (int cc = 0; cc < 4; cc++) {
                    float v = (cc == 0) ? v4.x : (cc == 1) ? v4.y : (cc == 2) ? v4.z : v4.w;
                    unsigned long long vd = pack2(v, v);
                    const unsigned long long* wr =
                        (const unsigned long long*)&ws[((g * 16 + c4 * 4 + cc) * 9 + k) * 18];
#pragma unroll
                    for (int o = 0; o < 9; o++) fma2(acc[o], vd, wr[o]);
                }
            }
        }
    }
    __syncthreads();                                   // done with ws reads
    float* red = pool;                                 // [4][128][18]
#pragma unroll
    for (int o = 0; o < 9; o++)
        *(float2*)&red[((g * 128 + pl) * 18) + 2 * o] = unpack2(acc[o]);
    __syncthreads();
    for (int i = threadIdx.x; i < 128 * 18; i += 512) {
        int p2 = i / 18, o = i % 18;
        float s = red[(0 * 128 + p2) * 18 + o] + red[(1 * 128 + p2) * 18 + o]
                + red[(2 * 128 + p2) * 18 + o] + red[(3 * 128 + p2) * 18 + o];
        int gp = blockIdx.x * 128 + p2;
        float tscale = 1.f + 16.f * g_thick[gp];
        g_off[(size_t)gp * 18 + o] = (s + off_b[o]) * tscale;
    }
}

// ---------------- deformable conv 3x3 (DCNv1) + bias + edge ----------------
__global__ __launch_bounds__(64) void deform_kernel(const float* __restrict__ deform_b) {
    __shared__ float ws[4096];                         // [c][o] for current tap
    int pix = blockIdx.x * 64 + threadIdx.x;           // 16384
    int b = pix >> 12, n = pix & 4095;
    int y = n >> 6, x = n & 63;
    unsigned long long acc[32];
#pragma unroll
    for (int o = 0; o < 32; o++) acc[o] = 0ull;
    const float* su = g_skip_u + (size_t)b * NPIX * 64;
    const float* offp = g_off + (size_t)pix * 18;
    for (int k = 0; k < 9; k++) {
        __syncthreads();
        for (int i = threadIdx.x * 4; i < 4096; i += 64 * 4)
            *(float4*)&ws[i] = *(const float4*)&g_dwT[k * 4096 + i];
        __syncthreads();
        float py = (float)(y + k / 3 - 1) + offp[2 * k];
        float px = (float)(x + k % 3 - 1) + offp[2 * k + 1];
        float y0f = floorf(py), x0f = floorf(px);
        float wy = py - y0f, wx = px - x0f;
        int y0 = (int)y0f, x0 = (int)x0f;
        int y1 = y0 + 1, x1 = x0 + 1;
        bool vy0 = (y0 >= 0 && y0 < 64), vy1 = (y1 >= 0 && y1 < 64);
        bool vx0 = (x0 >= 0 && x0 < 64), vx1 = (x1 >= 0 && x1 < 64);
        float w00 = (vy0 && vx0) ? (1.f - wy) * (1.f - wx) : 0.f;
        float w01 = (vy0 && vx1) ? (1.f - wy) * wx : 0.f;
        float w10 = (vy1 && vx0) ? wy * (1.f - wx) : 0.f;
        float w11 = (vy1 && vx1) ? wy * wx : 0.f;
        int yc0 = min(max(y0, 0), 63), yc1 = min(max(y1, 0), 63);
        int xc0 = min(max(x0, 0), 63), xc1 = min(max(x1, 0), 63);
        const float4* p00 = (const float4*)(su + (size_t)(yc0 * 64 + xc0) * 64);
        const float4* p01 = (const float4*)(su + (size_t)(yc0 * 64 + xc1) * 64);
        const float4* p10 = (const float4*)(su + (size_t)(yc1 * 64 + xc0) * 64);
        const float4* p11 = (const float4*)(su + (size_t)(yc1 * 64 + xc1) * 64);
        for (int c4 = 0; c4 < 16; c4++) {
            float4 a0 = p00[c4], a1 = p01[c4], a2 = p10[c4], a3 = p11[c4];
            float4 val4;
            val4.x = w00 * a0.x + w01 * a1.x + w10 * a2.x + w11 * a3.x;
            val4.y = w00 * a0.y + w01 * a1.y + w10 * a2.y + w11 * a3.y;
            val4.z = w00 * a0.z + w01 * a1.z + w10 * a2.z + w11 * a3.z;
            val4.w = w00 * a0.w + w01 * a1.w + w10 * a2.w + w11 * a3.w;
#pragma unroll
            for (int cc = 0; cc < 4; cc++) {
                float v = (cc == 0) ? val4.x : (cc == 1) ? val4.y : (cc == 2) ? val4.z : val4.w;
                unsigned long long vd = pack2(v, v);
                const unsigned long long* wr = (const unsigned long long*)&ws[(c4 * 4 + cc) * 64];
#pragma unroll
                for (int o = 0; o < 32; o++) fma2(acc[o], vd, wr[o]);
            }
        }
    }
    const float* ep = g_edge + (size_t)pix * 64;
    float* dp = g_d + (size_t)b * 64 * NPIX + n;
#pragma unroll
    for (int o2 = 0; o2 < 32; o2++) {
        float2 a2 = unpack2(acc[o2]);
        dp[(size_t)(2 * o2 + 0) * NPIX] = a2.x + deform_b[2 * o2 + 0] + ep[2 * o2 + 0];
        dp[(size_t)(2 * o2 + 1) * NPIX] = a2.y + deform_b[2 * o2 + 1] + ep[2 * o2 + 1];
    }
}

// ---------------- 1x1-conv GEMM on tensor cores (tf32 mma.sync, reg-prefetch) ----------------
__global__ __launch_bounds__(256) void gemm_tf32(const float* __restrict__ inA, int icA,
                                                 const float* __restrict__ inB, int IC,
                                                 const float* __restrict__ WT,
                                                 const float* __restrict__ bias, int OC,
                                                 const float* __restrict__ res,
                                                 float* __restrict__ out, int act) {
    __shared__ float Bs[16][136];
    __shared__ float Ws[16][72];
    int tid = threadIdx.x;
    int lane = tid & 31, w = tid >> 5;
    int g = lane >> 2, t = lane & 3;
    int wm = w >> 2, wn = w & 3;
    int n0 = blockIdx.x * 128;
    int oc0 = blockIdx.y * 64;
    int lb = n0 >> 12, ln = n0 & 4095;
    int icB = IC - icA;

    float acc[2][4][4];
#pragma unroll
    for (int mt = 0; mt < 2; mt++)
#pragma unroll
        for (int nt = 0; nt < 4; nt++)
#pragma unroll
            for (int j = 0; j < 4; j++) acc[mt][nt][j] = 0.f;

    int brow = tid >> 4, bcol = (tid & 15) * 8;
    int wrow = tid >> 4, wcol = (tid & 15) * 4;

    // prefetch registers for the upcoming tile
    float4 rB0, rB1, rW;
    {
        int ic = brow;
        const float* src;
        if (ic < icA) src = inA + ((size_t)lb * icA + ic) * NPIX + ln + bcol;
        else          src = inB + ((size_t)lb * icB + (ic - icA)) * NPIX + ln + bcol;
        rB0 = *(const float4*)src;
        rB1 = *(const float4*)(src + 4);
        const float* wsrc = WT + (size_t)wrow * OC + oc0 + wcol;
        if (oc0 + wcol + 3 < OC) {
            rW = *(const float4*)wsrc;
        } else {
            rW.x = (oc0 + wcol + 0 < OC) ? wsrc[0] : 0.f;
            rW.y = (oc0 + wcol + 1 < OC) ? wsrc[1] : 0.f;
            rW.z = (oc0 + wcol + 2 < OC) ? wsrc[2] : 0.f;
            rW.w = (oc0 + wcol + 3 < OC) ? wsrc[3] : 0.f;
        }
    }

    for (int k0 = 0; k0 < IC; k0 += 16) {
        __syncthreads();                 // previous tile's mma reads complete
        {
            float4 s0, s1;
            s0.x = __uint_as_float(tf32_of(rB0.x)); s0.y = __uint_as_float(tf32_of(rB0.y));
            s0.z = __uint_as_float(tf32_of(rB0.z)); s0.w = __uint_as_float(tf32_of(rB0.w));
            s1.x = __uint_as_float(tf32_of(rB1.x)); s1.y = __uint_as_float(tf32_of(rB1.y));
            s1.z = __uint_as_float(tf32_of(rB1.z)); s1.w = __uint_as_float(tf32_of(rB1.w));
            *(float4*)&Bs[brow][bcol] = s0;
            *(float4*)&Bs[brow][bcol + 4] = s1;
            *(float4*)&Ws[wrow][wcol] = rW;   // weights pre-rounded to tf32 in prep
        }
        __syncthreads();
        if (k0 + 16 < IC) {              // prefetch next tile while mma runs
            int ic = k0 + 16 + brow;
            const float* src;
            if (ic < icA) src = inA + ((size_t)lb * icA + ic) * NPIX + ln + bcol;
            else          src = inB + ((size_t)lb * icB + (ic - icA)) * NPIX + ln + bcol;
            rB0 = *(const float4*)src;
            rB1 = *(const float4*)(src + 4);
            const float* wsrc = WT + (size_t)(k0 + 16 + wrow) * OC + oc0 + wcol;
            if (oc0 + wcol + 3 < OC) {
                rW = *(const float4*)wsrc;
            } else {
                rW.x = (oc0 + wcol + 0 < OC) ? wsrc[0] : 0.f;
                rW.y = (oc0 + wcol + 1 < OC) ? wsrc[1] : 0.f;
                rW.z = (oc0 + wcol + 2 < OC) ? wsrc[2] : 0.f;
                rW.w = (oc0 + wcol + 3 < OC) ? wsrc[3] : 0.f;
            }
        }
#pragma unroll
        for (int ks = 0; ks < 2; ks++) {
            int kb = ks * 8;
            unsigned af[2][4];
#pragma unroll
            for (int mt = 0; mt < 2; mt++) {
                int row = wm * 32 + mt * 16;
                af[mt][0] = __float_as_uint(Ws[kb + t][row + g]);
                af[mt][1] = __float_as_uint(Ws[kb + t][row + g + 8]);
                af[mt][2] = __float_as_uint(Ws[kb + t + 4][row + g]);
                af[mt][3] = __float_as_uint(Ws[kb + t + 4][row + g + 8]);
            }
#pragma unroll
            for (int nt = 0; nt < 4; nt++) {
                int col = wn * 32 + nt * 8 + g;
                unsigned b0 = __float_as_uint(Bs[kb + t][col]);
                unsigned b1 = __float_as_uint(Bs[kb + t + 4][col]);
                mma_tf32(acc[0][nt], af[0], b0, b1);
                mma_tf32(acc[1][nt], af[1], b0, b1);
            }
        }
    }
#pragma unroll
    for (int mt = 0; mt < 2; mt++) {
#pragma unroll
        for (int nt = 0; nt < 4; nt++) {
            int col = ln + wn * 32 + nt * 8 + 2 * t;
#pragma unroll
            for (int r = 0; r < 2; r++) {
                int oc = oc0 + wm * 32 + mt * 16 + g + r * 8;
                if (oc < OC) {
                    float v0 = acc[mt][nt][r * 2 + 0] + bias[oc];
                    float v1 = acc[mt][nt][r * 2 + 1] + bias[oc];
                    if (act) { v0 = v0 * normcdff(v0); v1 = v1 * normcdff(v1); }
                    size_t oi = ((size_t)lb * OC + oc) * NPIX + col;
                    if (res) { v0 += res[oi]; v1 += res[oi + 1]; }
                    *(float2*)&out[oi] = make_float2(v0, v1);
                }
            }
        }
    }
}

// ---------------- flash attention (tf32 mma.sync): N=4096, d=32; q-tile 128 ----------------
#define FLASH_SM_FLOATS (32 * 72 + 64 * 41 + 8 * 16 * 72)
__global__ __launch_bounds__(256) void flash_kernel() {
    extern __shared__ float sm[];
    float* Kt_s = sm;                       // [ch][key] stride 72
    float* Vs_s = sm + 32 * 72;             // [key][ch] stride 41
    float* Ps_s = sm + 32 * 72 + 64 * 41;   // per-warp [16][72]
    int b = blockIdx.y;
    int q0 = blockIdx.x * 128;
    int tid = threadIdx.x;
    int w = tid >> 5, lane = tid & 31;
    int g = lane >> 2, t = lane & 3;
    const float* qkv = g_qkv + (size_t)b * 96 * NPIX;
    const float QSCALE = 1.4426950408889634f * 0.17677669529663687f;
    int qrow = q0 + w * 16 + g;

    unsigned qa[4][4];
#pragma unroll
    for (int kc = 0; kc < 4; kc++) {
        qa[kc][0] = tf32_of(qkv[(size_t)(kc * 8 + t) * NPIX + qrow] * QSCALE);
        qa[kc][1] = tf32_of(qkv[(size_t)(kc * 8 + t) * NPIX + qrow + 8] * QSCALE);
        qa[kc][2] = tf32_of(qkv[(size_t)(kc * 8 + t + 4) * NPIX + qrow] * QSCALE);
        qa[kc][3] = tf32_of(qkv[(size_t)(kc * 8 + t + 4) * NPIX + qrow + 8] * QSCALE);
    }

    float m0 = -INFINITY, m1 = -INFINITY, l0 = 0.f, l1 = 0.f;
    float o[4][4];
#pragma unroll
    for (int i = 0; i < 4; i++)
#pragma unroll
        for (int j = 0; j < 4; j++) o[i][j] = 0.f;
    float* Pw = Ps_s + w * 16 * 72;

    for (int kt = 0; kt < 64; kt++) {
        int k0 = kt * 64;
        __syncthreads();
        for (int i = tid; i < 2048; i += 256) {
            int ch = i >> 6, key = i & 63;
            Kt_s[ch * 72 + key] = __uint_as_float(tf32_of(qkv[(size_t)(32 + ch) * NPIX + k0 + key]));
            Vs_s[key * 41 + ch] = __uint_as_float(tf32_of(qkv[(size_t)(64 + ch) * NPIX + k0 + key]));
        }
        __syncthreads();

        float s[8][4];
#pragma unroll
        for (int nt = 0; nt < 8; nt++)
#pragma unroll
            for (int j = 0; j < 4; j++) s[nt][j] = 0.f;
#pragma unroll
        for (int nt = 0; nt < 8; nt++) {
#pragma unroll
            for (int kc = 0; kc < 4; kc++) {
                unsigned b0 = __float_as_uint(Kt_s[(kc * 8 + t) * 72 + nt * 8 + g]);
                unsigned b1 = __float_as_uint(Kt_s[(kc * 8 + t + 4) * 72 + nt * 8 + g]);
                mma_tf32(s[nt], qa[kc], b0, b1);
            }
        }

        float pm0 = -INFINITY, pm1 = -INFINITY;
#pragma unroll
        for (int nt = 0; nt < 8; nt++) {
            pm0 = fmaxf(pm0, fmaxf(s[nt][0], s[nt][1]));
            pm1 = fmaxf(pm1, fmaxf(s[nt][2], s[nt][3]));
        }
        pm0 = fmaxf(pm0, __shfl_xor_sync(0xffffffffu, pm0, 1, 4));
        pm0 = fmaxf(pm0, __shfl_xor_sync(0xffffffffu, pm0, 2, 4));
        pm1 = fmaxf(pm1, __shfl_xor_sync(0xffffffffu, pm1, 1, 4));
        pm1 = fmaxf(pm1, __shfl_xor_sync(0xffffffffu, pm1, 2, 4));
        float mn0 = fmaxf(m0, pm0), mn1 = fmaxf(m1, pm1);
        float al0 = exp2f(m0 - mn0), al1 = exp2f(m1 - mn1);
        m0 = mn0; m1 = mn1;
        l0 *= al0; l1 *= al1;
#pragma unroll
        for (int c = 0; c < 4; c++) {
            o[c][0] *= al0; o[c][1] *= al0;
            o[c][2] *= al1; o[c][3] *= al1;
        }
        float ps0 = 0.f, ps1 = 0.f;
#pragma unroll
        for (int nt = 0; nt < 8; nt++) {
            float p0 = exp2f(s[nt][0] - mn0);
            float p1 = exp2f(s[nt][1] - mn0);
            float p2 = exp2f(s[nt][2] - mn1);
            float p3 = exp2f(s[nt][3] - mn1);
            ps0 += p0 + p1; ps1 += p2 + p3;
            uint2 lo = make_uint2(tf32_of(p0), tf32_of(p1));
            uint2 hi = make_uint2(tf32_of(p2), tf32_of(p3));
            *(uint2*)&Pw[g * 72 + nt * 8 + 2 * t] = lo;
            *(uint2*)&Pw[(g + 8) * 72 + nt * 8 + 2 * t] = hi;
        }
        ps0 += __shfl_xor_sync(0xffffffffu, ps0, 1, 4);
        ps0 += __shfl_xor_sync(0xffffffffu, ps0, 2, 4);
        ps1 += __shfl_xor_sync(0xffffffffu, ps1, 1, 4);
        ps1 += __shfl_xor_sync(0xffffffffu, ps1, 2, 4);
        l0 += ps0; l1 += ps1;
        __syncwarp();

#pragma unroll
        for (int c = 0; c < 8; c++) {
            unsigned pa[4];
            pa[0] = __float_as_uint(Pw[g * 72 + c * 8 + t]);
            pa[1] = __float_as_uint(Pw[(g + 8) * 72 + c * 8 + t]);
            pa[2] = __float_as_uint(Pw[g * 72 + c * 8 + t + 4]);
            pa[3] = __float_as_uint(Pw[(g + 8) * 72 + c * 8 + t + 4]);
#pragma unroll
            for (int nt2 = 0; nt2 < 4; nt2++) {
                unsigned b0 = __float_as_uint(Vs_s[(c * 8 + t) * 41 + nt2 * 8 + g]);
                unsigned b1 = __float_as_uint(Vs_s[(c * 8 + t + 4) * 41 + nt2 * 8 + g]);
                mma_tf32(o[nt2], pa, b0, b1);
            }
        }
        __syncwarp();
    }

    float inv0 = 1.f / l0, inv1 = 1.f / l1;
    float* av = g_av + (size_t)b * 32 * NPIX;
#pragma unroll
    for (int nt2 = 0; nt2 < 4; nt2++) {
        int ch = nt2 * 8 + 2 * t;
        av[(size_t)ch * NPIX + qrow]           = o[nt2][0] * inv0;
        av[(size_t)(ch + 1) * NPIX + qrow]     = o[nt2][1] * inv0;
        av[(size_t)ch * NPIX + qrow + 8]       = o[nt2][2] * inv1;
        av[(size_t)(ch + 1) * NPIX + qrow + 8] = o[nt2][3] * inv1;
    }
}

// ---------------- layernorm over 64 channels per pixel ----------------
__global__ void ln_kernel(const float* __restrict__ ln_g, const float* __restrict__ ln_b) {
    int p = blockIdx.x * 256 + threadIdx.x;
    int b = p >> 12, n = p & 4095;
    const float* ep = g_e + (size_t)b * 64 * NPIX + n;
    float v[64], mu = 0.f;
#pragma unroll
    for (int c = 0; c < 64; c++) { v[c] = ep[(size_t)c * NPIX]; mu += v[c]; }
    mu *= (1.f / 64.f);
    float var = 0.f;
#pragma unroll
    for (int c = 0; c < 64; c++) { float d = v[c] - mu; var += d * d; }
    var *= (1.f / 64.f);
    float inv = rsqrtf(var + 1e-5f);
    float* hp = g_h + (size_t)b * 64 * NPIX + n;
#pragma unroll
    for (int c = 0; c < 64; c++) hp[(size_t)c * NPIX] = (v[c] - mu) * inv * ln_g[c] + ln_b[c];
}

// ---------------- depthwise 3x3 conv + bias + GELU ----------------
__global__ void dw_kernel(const float* __restrict__ dw_w, const float* __restrict__ dw_b) {
    int idx = blockIdx.x * 256 + threadIdx.x;          // 4*256*4096
    int n = idx & 4095, c = (idx >> 12) & 255;
    int y = n >> 6, x = n & 63;
    const float* hp = g_h1 + (size_t)(idx >> 12) * NPIX;
    const float* w = dw_w + c * 9;
    float a = 0.f;
#pragma unroll
    for (int ky = 0; ky < 3; ky++) {
        int yy = y + ky - 1;
        if (yy < 0 || yy >= 64) continue;
#pragma unroll
        for (int kx = 0; kx < 3; kx++) {
            int xx = x + kx - 1;
            if (xx < 0 || xx >= 64) continue;
            a += hp[yy * 64 + xx] * w[ky * 3 + kx];
        }
    }
    a += dw_b[c];
    g_h2[idx] = a * normcdff(a);
}

// ---------------- host launcher ----------------
extern "C" void kernel_launch(void* const* d_in, const int* in_sizes, int n_in,
                              void* d_out, int out_size) {
    (void)in_sizes; (void)n_in; (void)out_size;
    const float* x       = (const float*)d_in[0];
    const float* skip    = (const float*)d_in[1];
    const float* qkv_w   = (const float*)d_in[2];
    const float* qkv_b   = (const float*)d_in[3];
    const float* proj_w  = (const float*)d_in[4];
    const float* proj_b  = (const float*)d_in[5];
    const float* edge_w  = (const float*)d_in[6];
    const float* thick_w = (const float*)d_in[7];
    const float* thick_b = (const float*)d_in[8];
    const float* off_w   = (const float*)d_in[9];
    const float* off_b   = (const float*)d_in[10];
    const float* deform_w= (const float*)d_in[11];
    const float* deform_b= (const float*)d_in[12];
    const float* ln_g    = (const float*)d_in[13];
    const float* ln_b    = (const float*)d_in[14];
    const float* mlp1_w  = (const float*)d_in[15];
    const float* mlp1_b  = (const float*)d_in[16];
    const float* dw_w    = (const float*)d_in[17];
    const float* dw_b    = (const float*)d_in[18];
    const float* mlp2_w  = (const float*)d_in[19];
    const float* mlp2_b  = (const float*)d_in[20];
    const float* down_w  = (const float*)d_in[21];
    const float* down_b  = (const float*)d_in[22];
    const float* up_w    = (const float*)d_in[23];
    const float* up_b    = (const float*)d_in[24];
    float* out = (float*)d_out;

    float *p_qkv, *p_av, *p_x2, *p_d, *p_e, *p_h, *p_h1, *p_h2, *p_t;
    float *p_qkvWT, *p_projWT, *p_downWT, *p_mlp1WT, *p_mlp2WT, *p_upWT;
    cudaGetSymbolAddress((void**)&p_qkv,    g_qkv);
    cudaGetSymbolAddress((void**)&p_av,     g_av);
    cudaGetSymbolAddress((void**)&p_x2,     g_x2);
    cudaGetSymbolAddress((void**)&p_d,      g_d);
    cudaGetSymbolAddress((void**)&p_e,      g_e);
    cudaGetSymbolAddress((void**)&p_h,      g_h);
    cudaGetSymbolAddress((void**)&p_h1,     g_h1);
    cudaGetSymbolAddress((void**)&p_h2,     g_h2);
    cudaGetSymbolAddress((void**)&p_t,      g_t);
    cudaGetSymbolAddress((void**)&p_qkvWT,  g_qkvWT);
    cudaGetSymbolAddress((void**)&p_projWT, g_projWT);
    cudaGetSymbolAddress((void**)&p_downWT, g_downWT);
    cudaGetSymbolAddress((void**)&p_mlp1WT, g_mlp1WT);
    cudaGetSymbolAddress((void**)&p_mlp2WT, g_mlp2WT);
    cudaGetSymbolAddress((void**)&p_upWT,   g_upWT);

    // one-time stream/event creation (host resources, not device memory).
    // If creation fails for any reason, fall back to fully-serial launches.
    static cudaStream_t s1 = nullptr;
    static cudaEvent_t ev_fork = nullptr, ev_join = nullptr;
    static int use_streams = -1;
    if (use_streams < 0) {
        cudaError_t e1 = cudaStreamCreateWithFlags(&s1, cudaStreamNonBlocking);
        cudaError_t e2 = cudaEventCreateWithFlags(&ev_fork, cudaEventDisableTiming);
        cudaError_t e3 = cudaEventCreateWithFlags(&ev_join, cudaEventDisableTiming);
        use_streams = (e1 == cudaSuccess && e2 == cudaSuccess && e3 == cudaSuccess) ? 1 : 0;
        cudaFuncSetAttribute(flash_kernel, cudaFuncAttributeMaxDynamicSharedMemorySize,
                             FLASH_SM_FLOATS * 4);
    }
    const int flash_smem = FLASH_SM_FLOATS * 4;

    prep_kernel<<<128, 256>>>(qkv_w, proj_w, down_w, mlp1_w, mlp2_w, up_w, deform_w);

    if (use_streams) {
        // fork: skip path on s1, attention path on default stream
        cudaEventRecord(ev_fork, 0);
        cudaStreamWaitEvent(s1, ev_fork, 0);

        upsample_kernel<<<dim3(64, 4), 64, 0, s1>>>(skip, thick_w, thick_b);
        edge_kernel<<<4096, 256, 0, s1>>>(edge_w);
        off_kernel<<<128, 512, 0, s1>>>(off_w, off_b);
        deform_kernel<<<256, 64, 0, s1>>>(deform_b);
        cudaEventRecord(ev_join, s1);

        gemm_tf32<<<dim3(128, 2), 256>>>(x, 256, nullptr, 256, p_qkvWT, qkv_b, 96, nullptr, p_qkv, 0);
        flash_kernel<<<dim3(32, 4), 256, flash_smem>>>();
        gemm_tf32<<<dim3(128, 4), 256>>>(p_av, 32, nullptr, 32, p_projWT, proj_b, 256, x, p_x2, 0);

        // join: down needs both x2 (default stream) and d (s1)
        cudaStreamWaitEvent(0, ev_join, 0);
    } else {
        upsample_kernel<<<dim3(64, 4), 64>>>(skip, thick_w, thick_b);
        edge_kernel<<<4096, 256>>>(edge_w);
        off_kernel<<<128, 512>>>(off_w, off_b);
        deform_kernel<<<256, 64>>>(deform_b);
        gemm_tf32<<<dim3(128, 2), 256>>>(x, 256, nullptr, 256, p_qkvWT, qkv_b, 96, nullptr, p_qkv, 0);
        flash_kernel<<<dim3(32, 4), 256, flash_smem>>>();
        gemm_tf32<<<dim3(128, 4), 256>>>(p_av, 32, nullptr, 32, p_projWT, proj_b, 256, x, p_x2, 0);
    }

    gemm_tf32<<<dim3(128, 1), 256>>>(p_x2, 256, p_d, 320, p_downWT, down_b, 64, nullptr, p_e, 0);
    ln_kernel<<<64, 256>>>(ln_g, ln_b);
    gemm_tf32<<<dim3(128, 4), 256>>>(p_h, 64, nullptr, 64, p_mlp1WT, mlp1_b, 256, nullptr, p_h1, 1);
    dw_kernel<<<16384, 256>>>(dw_w, dw_b);
    gemm_tf32<<<dim3(128, 1), 256>>>(p_h2, 256, nullptr, 256, p_mlp2WT, mlp2_b, 64, p_e, p_t, 0);
    gemm_tf32<<<dim3(128, 4), 256>>>(p_t, 64, nullptr, 64, p_upWT, up_b, 256, nullptr, out, 0);
}

// round 17
// speedup vs baseline: 1.2696x; 1.0347x over previous
#include <cuda_runtime.h>
#include <math.h>

#define NPIX 4096

// ---------------- f32x2 packed helpers (sm_100+) ----------------
__device__ __forceinline__ unsigned long long pack2(float lo, float hi) {
    unsigned long long r;
    asm("mov.b64 %0, {%1, %2};" : "=l"(r) : "f"(lo), "f"(hi));
    return r;
}
__device__ __forceinline__ float2 unpack2(unsigned long long v) {
    float2 r;
    asm("mov.b64 {%0, %1}, %2;" : "=f"(r.x), "=f"(r.y) : "l"(v));
    return r;
}
__device__ __forceinline__ void fma2(unsigned long long& d, unsigned long long a, unsigned long long b) {
    asm("fma.rn.f32x2 %0, %1, %2, %3;" : "=l"(d) : "l"(a), "l"(b), "l"(d));
}

// ---------------- tf32 mma helpers ----------------
__device__ __forceinline__ unsigned tf32_of(float f) {
    unsigned r;
    asm("cvt.rna.tf32.f32 %0, %1;" : "=r"(r) : "f"(f));
    return r;
}
__device__ __forceinline__ void mma_tf32(float* d, const unsigned* a, unsigned b0, unsigned b1) {
    asm volatile(
        "mma.sync.aligned.m16n8k8.row.col.f32.tf32.tf32.f32 "
        "{%0,%1,%2,%3}, {%4,%5,%6,%7}, {%8,%9}, {%0,%1,%2,%3};"
        : "+f"(d[0]), "+f"(d[1]), "+f"(d[2]), "+f"(d[3])
        : "r"(a[0]), "r"(a[1]), "r"(a[2]), "r"(a[3]), "r"(b0), "r"(b1));
}

// ---------------- scratch (device globals; allocation forbidden) ----------------
__device__ __align__(128) float g_skip_u[4 * NPIX * 64];   // NHWC [b][n][c]
__device__ __align__(128) float g_mean  [4 * NPIX];
__device__ __align__(128) float g_thick [4 * NPIX];
__device__ __align__(128) float g_edge  [4 * NPIX * 64];   // NHWC [b][n][c]
__device__ __align__(128) float g_off   [4 * NPIX * 18];   // NHWC [b][n][18]
__device__ __align__(128) float g_d     [4 * 64 * NPIX];   // NCHW
__device__ __align__(128) float g_qkv   [4 * 96 * NPIX];
__device__ __align__(128) float g_av    [4 * 32 * NPIX];
__device__ __align__(128) float g_x2    [4 * 256 * NPIX];
__device__ __align__(128) float g_e     [4 * 64 * NPIX];
__device__ __align__(128) float g_h     [4 * 64 * NPIX];
__device__ __align__(128) float g_h1    [4 * 256 * NPIX];
__device__ __align__(128) float g_h2    [4 * 256 * NPIX];
__device__ __align__(128) float g_t     [4 * 64 * NPIX];
// transposed weights [IC][OC], pre-rounded to tf32
__device__ __align__(128) float g_qkvWT [256 * 96];
__device__ __align__(128) float g_projWT[32 * 256];
__device__ __align__(128) float g_downWT[320 * 64];
__device__ __align__(128) float g_mlp1WT[64 * 256];
__device__ __align__(128) float g_mlp2WT[256 * 64];
__device__ __align__(128) float g_upWT  [64 * 256];
__device__ __align__(128) float g_dwT   [9 * 64 * 64];   // deform_w as [k][c][o] (fp32)

// ---------------- prep: transpose weights (GEMM weights stored as tf32 bits) ----------------
__global__ void prep_kernel(const float* __restrict__ qkv_w, const float* __restrict__ proj_w,
                            const float* __restrict__ down_w, const float* __restrict__ mlp1_w,
                            const float* __restrict__ mlp2_w, const float* __restrict__ up_w,
                            const float* __restrict__ deform_w) {
    int t0 = blockIdx.x * blockDim.x + threadIdx.x;
    int stride = gridDim.x * blockDim.x;
    for (int i = t0; i < 256 * 96; i += stride) { int ic = i / 96,  oc = i % 96;  g_qkvWT[i]  = __uint_as_float(tf32_of(qkv_w[oc * 256 + ic])); }
    for (int i = t0; i < 32 * 256; i += stride) { int ic = i / 256, oc = i % 256; g_projWT[i] = __uint_as_float(tf32_of(proj_w[oc * 32 + ic])); }
    for (int i = t0; i < 320 * 64; i += stride) { int ic = i / 64,  oc = i % 64;  g_downWT[i] = __uint_as_float(tf32_of(down_w[oc * 320 + ic])); }
    for (int i = t0; i < 64 * 256; i += stride) { int ic = i / 256, oc = i % 256; g_mlp1WT[i] = __uint_as_float(tf32_of(mlp1_w[oc * 64 + ic])); }
    for (int i = t0; i < 256 * 64; i += stride) { int ic = i / 64,  oc = i % 64;  g_mlp2WT[i] = __uint_as_float(tf32_of(mlp2_w[oc * 256 + ic])); }
    for (int i = t0; i < 64 * 256; i += stride) { int ic = i / 256, oc = i % 256; g_upWT[i]   = __uint_as_float(tf32_of(up_w[oc * 64 + ic])); }
    for (int i = t0; i < 9 * 64 * 64; i += stride) {
        int k = i >> 12, c = (i >> 6) & 63, o = i & 63;
        g_dwT[i] = deform_w[(o * 64 + c) * 9 + k];
    }
}

// ---------------- bilinear upsample (half-pixel) + channel mean + thick (NHWC out) ----------------
__global__ void upsample_kernel(const float* __restrict__ skip, const float* __restrict__ thick_w,
                                const float* __restrict__ thick_b) {
    int b = blockIdx.y, y = blockIdx.x, x = threadIdx.x;
    float sy = fminf(fmaxf(0.5f * y - 0.25f, 0.f), 31.f);
    float sx = fminf(fmaxf(0.5f * x - 0.25f, 0.f), 31.f);
    int y0 = (int)sy, x0 = (int)sx;
    int y1 = min(y0 + 1, 31), x1 = min(x0 + 1, 31);
    float wy = sy - (float)y0, wx = sx - (float)x0;
    float w00 = (1.f - wy) * (1.f - wx), w01 = (1.f - wy) * wx;
    float w10 = wy * (1.f - wx),         w11 = wy * wx;
    const float* sp = skip + (size_t)b * 64 * 1024;
    int pix = b * NPIX + y * 64 + x;
    float* up = g_skip_u + (size_t)pix * 64;
    float sum = 0.f, tsum = 0.f;
    for (int c = 0; c < 64; c++) {
        const float* p = sp + c * 1024;
        float v = w00 * p[y0 * 32 + x0] + w01 * p[y0 * 32 + x1]
                + w10 * p[y1 * 32 + x0] + w11 * p[y1 * 32 + x1];
        up[c] = v;
        sum += v;
        tsum += v * thick_w[c];
    }
    g_mean[pix] = sum * (1.f / 64.f);
    g_thick[pix] = 1.f / (1.f + expf(-(tsum + thick_b[0])));
}

// ---------------- edge conv: 3x3, 1 -> 64 ch, zero pad, no bias (NHWC out) ----------------
__global__ void edge_kernel(const float* __restrict__ edge_w) {
    int idx = blockIdx.x * 256 + threadIdx.x;          // 4*4096*64, oc fastest
    int oc = idx & 63, n = (idx >> 6) & 4095, b = idx >> 18;
    int y = n >> 6, x = n & 63;
    const float* mp = g_mean + b * NPIX;
    float a = 0.f;
#pragma unroll
    for (int ky = 0; ky < 3; ky++) {
        int yy = y + ky - 1;
        if (yy < 0 || yy >= 64) continue;
#pragma unroll
        for (int kx = 0; kx < 3; kx++) {
            int xx = x + kx - 1;
            if (xx < 0 || xx >= 64) continue;
            a += mp[yy * 64 + xx] * edge_w[oc * 9 + ky * 3 + kx];
        }
    }
    g_edge[idx] = a;
}

// ---------------- offset conv: 3x3, 64 -> 18, * (1 + 16*thick) ----------------
__global__ __launch_bounds__(512) void off_kernel(const float* __restrict__ off_w,
                                                  const float* __restrict__ off_b) {
    __shared__ float pool[64 * 9 * 18];                // ws, then reused as red[4*128*18]
    float* ws = pool;
    for (int i = threadIdx.x; i < 64 * 9 * 18; i += 512) {
        int o = i % 18, ck = i / 18;
        ws[i] = off_w[o * 576 + ck];                   // [c][k][o]
    }
    __syncthreads();
    int pl = threadIdx.x & 127, g = threadIdx.x >> 7;
    int pix = blockIdx.x * 128 + pl;
    int b = pix >> 12, n = pix & 4095;
    int y = n >> 6, x = n & 63;
    unsigned long long acc[9];
#pragma unroll
    for (int o = 0; o < 9; o++) acc[o] = 0ull;
    const float* ep = g_edge + (size_t)b * NPIX * 64;
#pragma unroll
    for (int ky = 0; ky < 3; ky++) {
        int yy = y + ky - 1;
        if (yy < 0 || yy >= 64) continue;
#pragma unroll
        for (int kx = 0; kx < 3; kx++) {
            int xx = x + kx - 1;
            if (xx < 0 || xx >= 64) continue;
            int k = ky * 3 + kx;
            const float4* col = (const float4*)(ep + (size_t)(yy * 64 + xx) * 64 + g * 16);
#pragma unroll
            for (int c4 = 0; c4 < 4; c4++) {
                float4 v4 = col[c4];
#pragma unroll
                for (int cc = 0; cc < 4; cc++) {
                    float v = (cc == 0) ? v4.x : (cc == 1) ? v4.y : (cc == 2) ? v4.z : v4.w;
                    unsigned long long vd = pack2(v, v);
                    const unsigned long long* wr =
                        (const unsigned long long*)&ws[((g * 16 + c4 * 4 + cc) * 9 + k) * 18];
#pragma unroll
                    for (int o = 0; o < 9; o++) fma2(acc[o], vd, wr[o]);
                }
            }
        }
    }
    __syncthreads();                                   // done with ws reads
    float* red = pool;                                 // [4][128][18]
#pragma unroll
    for (int o = 0; o < 9; o++)
        *(float2*)&red[((g * 128 + pl) * 18) + 2 * o] = unpack2(acc[o]);
    __syncthreads();
    for (int i = threadIdx.x; i < 128 * 18; i += 512) {
        int p2 = i / 18, o = i % 18;
        float s = red[(0 * 128 + p2) * 18 + o] + red[(1 * 128 + p2) * 18 + o]
                + red[(2 * 128 + p2) * 18 + o] + red[(3 * 128 + p2) * 18 + o];
        int gp = blockIdx.x * 128 + p2;
        float tscale = 1.f + 16.f * g_thick[gp];
        g_off[(size_t)gp * 18 + o] = (s + off_b[o]) * tscale;
    }
}

// ---------------- deformable conv 3x3 (DCNv1) + bias + edge ----------------
__global__ __launch_bounds__(64) void deform_kernel(const float* __restrict__ deform_b) {
    __shared__ float ws[4096];                         // [c][o] for current tap
    int pix = blockIdx.x * 64 + threadIdx.x;           // 16384
    int b = pix >> 12, n = pix & 4095;
    int y = n >> 6, x = n & 63;
    unsigned long long acc[32];
#pragma unroll
    for (int o = 0; o < 32; o++) acc[o] = 0ull;
    const float* su = g_skip_u + (size_t)b * NPIX * 64;
    const float* offp = g_off + (size_t)pix * 18;
    for (int k = 0; k < 9; k++) {
        __syncthreads();
        for (int i = threadIdx.x * 4; i < 4096; i += 64 * 4)
            *(float4*)&ws[i] = *(const float4*)&g_dwT[k * 4096 + i];
        __syncthreads();
        float py = (float)(y + k / 3 - 1) + offp[2 * k];
        float px = (float)(x + k % 3 - 1) + offp[2 * k + 1];
        float y0f = floorf(py), x0f = floorf(px);
        float wy = py - y0f, wx = px - x0f;
        int y0 = (int)y0f, x0 = (int)x0f;
        int y1 = y0 + 1, x1 = x0 + 1;
        bool vy0 = (y0 >= 0 && y0 < 64), vy1 = (y1 >= 0 && y1 < 64);
        bool vx0 = (x0 >= 0 && x0 < 64), vx1 = (x1 >= 0 && x1 < 64);
        float w00 = (vy0 && vx0) ? (1.f - wy) * (1.f - wx) : 0.f;
        float w01 = (vy0 && vx1) ? (1.f - wy) * wx : 0.f;
        float w10 = (vy1 && vx0) ? wy * (1.f - wx) : 0.f;
        float w11 = (vy1 && vx1) ? wy * wx : 0.f;
        int yc0 = min(max(y0, 0), 63), yc1 = min(max(y1, 0), 63);
        int xc0 = min(max(x0, 0), 63), xc1 = min(max(x1, 0), 63);
        const float4* p00 = (const float4*)(su + (size_t)(yc0 * 64 + xc0) * 64);
        const float4* p01 = (const float4*)(su + (size_t)(yc0 * 64 + xc1) * 64);
        const float4* p10 = (const float4*)(su + (size_t)(yc1 * 64 + xc0) * 64);
        const float4* p11 = (const float4*)(su + (size_t)(yc1 * 64 + xc1) * 64);
        for (int c4 = 0; c4 < 16; c4++) {
            float4 a0 = p00[c4], a1 = p01[c4], a2 = p10[c4], a3 = p11[c4];
            float4 val4;
            val4.x = w00 * a0.x + w01 * a1.x + w10 * a2.x + w11 * a3.x;
            val4.y = w00 * a0.y + w01 * a1.y + w10 * a2.y + w11 * a3.y;
            val4.z = w00 * a0.z + w01 * a1.z + w10 * a2.z + w11 * a3.z;
            val4.w = w00 * a0.w + w01 * a1.w + w10 * a2.w + w11 * a3.w;
#pragma unroll
            for (int cc = 0; cc < 4; cc++) {
                float v = (cc == 0) ? val4.x : (cc == 1) ? val4.y : (cc == 2) ? val4.z : val4.w;
                unsigned long long vd = pack2(v, v);
                const unsigned long long* wr = (const unsigned long long*)&ws[(c4 * 4 + cc) * 64];
#pragma unroll
                for (int o = 0; o < 32; o++) fma2(acc[o], vd, wr[o]);
            }
        }
    }
    const float* ep = g_edge + (size_t)pix * 64;
    float* dp = g_d + (size_t)b * 64 * NPIX + n;
#pragma unroll
    for (int o2 = 0; o2 < 32; o2++) {
        float2 a2 = unpack2(acc[o2]);
        dp[(size_t)(2 * o2 + 0) * NPIX] = a2.x + deform_b[2 * o2 + 0] + ep[2 * o2 + 0];
        dp[(size_t)(2 * o2 + 1) * NPIX] = a2.y + deform_b[2 * o2 + 1] + ep[2 * o2 + 1];
    }
}

// ---------------- 1x1-conv GEMM on tensor cores (tf32 mma.sync, reg-prefetch) ----------------
__global__ __launch_bounds__(256) void gemm_tf32(const float* __restrict__ inA, int icA,
                                                 const float* __restrict__ inB, int IC,
                                                 const float* __restrict__ WT,
                                                 const float* __restrict__ bias, int OC,
                                                 const float* __restrict__ res,
                                                 float* __restrict__ out, int act) {
    __shared__ float Bs[16][136];
    __shared__ float Ws[16][72];
    int tid = threadIdx.x;
    int lane = tid & 31, w = tid >> 5;
    int g = lane >> 2, t = lane & 3;
    int wm = w >> 2, wn = w & 3;
    int n0 = blockIdx.x * 128;
    int oc0 = blockIdx.y * 64;
    int lb = n0 >> 12, ln = n0 & 4095;
    int icB = IC - icA;

    float acc[2][4][4];
#pragma unroll
    for (int mt = 0; mt < 2; mt++)
#pragma unroll
        for (int nt = 0; nt < 4; nt++)
#pragma unroll
            for (int j = 0; j < 4; j++) acc[mt][nt][j] = 0.f;

    int brow = tid >> 4, bcol = (tid & 15) * 8;
    int wrow = tid >> 4, wcol = (tid & 15) * 4;

    float4 rB0, rB1, rW;
    {
        int ic = brow;
        const float* src;
        if (ic < icA) src = inA + ((size_t)lb * icA + ic) * NPIX + ln + bcol;
        else          src = inB + ((size_t)lb * icB + (ic - icA)) * NPIX + ln + bcol;
        rB0 = *(const float4*)src;
        rB1 = *(const float4*)(src + 4);
        const float* wsrc = WT + (size_t)wrow * OC + oc0 + wcol;
        if (oc0 + wcol + 3 < OC) {
            rW = *(const float4*)wsrc;
        } else {
            rW.x = (oc0 + wcol + 0 < OC) ? wsrc[0] : 0.f;
            rW.y = (oc0 + wcol + 1 < OC) ? wsrc[1] : 0.f;
            rW.z = (oc0 + wcol + 2 < OC) ? wsrc[2] : 0.f;
            rW.w = (oc0 + wcol + 3 < OC) ? wsrc[3] : 0.f;
        }
    }

    for (int k0 = 0; k0 < IC; k0 += 16) {
        __syncthreads();
        {
            float4 s0, s1;
            s0.x = __uint_as_float(tf32_of(rB0.x)); s0.y = __uint_as_float(tf32_of(rB0.y));
            s0.z = __uint_as_float(tf32_of(rB0.z)); s0.w = __uint_as_float(tf32_of(rB0.w));
            s1.x = __uint_as_float(tf32_of(rB1.x)); s1.y = __uint_as_float(tf32_of(rB1.y));
            s1.z = __uint_as_float(tf32_of(rB1.z)); s1.w = __uint_as_float(tf32_of(rB1.w));
            *(float4*)&Bs[brow][bcol] = s0;
            *(float4*)&Bs[brow][bcol + 4] = s1;
            *(float4*)&Ws[wrow][wcol] = rW;
        }
        __syncthreads();
        if (k0 + 16 < IC) {
            int ic = k0 + 16 + brow;
            const float* src;
            if (ic < icA) src = inA + ((size_t)lb * icA + ic) * NPIX + ln + bcol;
            else          src = inB + ((size_t)lb * icB + (ic - icA)) * NPIX + ln + bcol;
            rB0 = *(const float4*)src;
            rB1 = *(const float4*)(src + 4);
            const float* wsrc = WT + (size_t)(k0 + 16 + wrow) * OC + oc0 + wcol;
            if (oc0 + wcol + 3 < OC) {
                rW = *(const float4*)wsrc;
            } else {
                rW.x = (oc0 + wcol + 0 < OC) ? wsrc[0] : 0.f;
                rW.y = (oc0 + wcol + 1 < OC) ? wsrc[1] : 0.f;
                rW.z = (oc0 + wcol + 2 < OC) ? wsrc[2] : 0.f;
                rW.w = (oc0 + wcol + 3 < OC) ? wsrc[3] : 0.f;
            }
        }
#pragma unroll
        for (int ks = 0; ks < 2; ks++) {
            int kb = ks * 8;
            unsigned af[2][4];
#pragma unroll
            for (int mt = 0; mt < 2; mt++) {
                int row = wm * 32 + mt * 16;
                af[mt][0] = __float_as_uint(Ws[kb + t][row + g]);
                af[mt][1] = __float_as_uint(Ws[kb + t][row + g + 8]);
                af[mt][2] = __float_as_uint(Ws[kb + t + 4][row + g]);
                af[mt][3] = __float_as_uint(Ws[kb + t + 4][row + g + 8]);
            }
#pragma unroll
            for (int nt = 0; nt < 4; nt++) {
                int col = wn * 32 + nt * 8 + g;
                unsigned b0 = __float_as_uint(Bs[kb + t][col]);
                unsigned b1 = __float_as_uint(Bs[kb + t + 4][col]);
                mma_tf32(acc[0][nt], af[0], b0, b1);
                mma_tf32(acc[1][nt], af[1], b0, b1);
            }
        }
    }
#pragma unroll
    for (int mt = 0; mt < 2; mt++) {
#pragma unroll
        for (int nt = 0; nt < 4; nt++) {
            int col = ln + wn * 32 + nt * 8 + 2 * t;
#pragma unroll
            for (int r = 0; r < 2; r++) {
                int oc = oc0 + wm * 32 + mt * 16 + g + r * 8;
                if (oc < OC) {
                    float v0 = acc[mt][nt][r * 2 + 0] + bias[oc];
                    float v1 = acc[mt][nt][r * 2 + 1] + bias[oc];
                    if (act) { v0 = v0 * normcdff(v0); v1 = v1 * normcdff(v1); }
                    size_t oi = ((size_t)lb * OC + oc) * NPIX + col;
                    if (res) { v0 += res[oi]; v1 += res[oi + 1]; }
                    *(float2*)&out[oi] = make_float2(v0, v1);
                }
            }
        }
    }
}

// ---------------- flash attention (tf32 mma.sync): N=4096, d=32; q-tile 128 ----------------
#define FLASH_SM_FLOATS (32 * 72 + 64 * 41 + 8 * 16 * 72)
__global__ __launch_bounds__(256) void flash_kernel() {
    extern __shared__ float sm[];
    float* Kt_s = sm;                       // [ch][key] stride 72
    float* Vs_s = sm + 32 * 72;             // [key][ch] stride 41
    float* Ps_s = sm + 32 * 72 + 64 * 41;   // per-warp [16][72]
    int b = blockIdx.y;
    int q0 = blockIdx.x * 128;
    int tid = threadIdx.x;
    int w = tid >> 5, lane = tid & 31;
    int g = lane >> 2, t = lane & 3;
    const float* qkv = g_qkv + (size_t)b * 96 * NPIX;
    const float QSCALE = 1.4426950408889634f * 0.17677669529663687f;
    int qrow = q0 + w * 16 + g;

    unsigned qa[4][4];
#pragma unroll
    for (int kc = 0; kc < 4; kc++) {
        qa[kc][0] = tf32_of(qkv[(size_t)(kc * 8 + t) * NPIX + qrow] * QSCALE);
        qa[kc][1] = tf32_of(qkv[(size_t)(kc * 8 + t) * NPIX + qrow + 8] * QSCALE);
        qa[kc][2] = tf32_of(qkv[(size_t)(kc * 8 + t + 4) * NPIX + qrow] * QSCALE);
        qa[kc][3] = tf32_of(qkv[(size_t)(kc * 8 + t + 4) * NPIX + qrow + 8] * QSCALE);
    }

    float m0 = -INFINITY, m1 = -INFINITY, l0 = 0.f, l1 = 0.f;
    float o[4][4];
#pragma unroll
    for (int i = 0; i < 4; i++)
#pragma unroll
        for (int j = 0; j < 4; j++) o[i][j] = 0.f;
    float* Pw = Ps_s + w * 16 * 72;

    for (int kt = 0; kt < 64; kt++) {
        int k0 = kt * 64;
        __syncthreads();
        for (int i = tid; i < 2048; i += 256) {
            int ch = i >> 6, key = i & 63;
            Kt_s[ch * 72 + key] = __uint_as_float(tf32_of(qkv[(size_t)(32 + ch) * NPIX + k0 + key]));
            Vs_s[key * 41 + ch] = __uint_as_float(tf32_of(qkv[(size_t)(64 + ch) * NPIX + k0 + key]));
        }
        __syncthreads();

        float s[8][4];
#pragma unroll
        for (int nt = 0; nt < 8; nt++)
#pragma unroll
            for (int j = 0; j < 4; j++) s[nt][j] = 0.f;
#pragma unroll
        for (int nt = 0; nt < 8; nt++) {
#pragma unroll
            for (int kc = 0; kc < 4; kc++) {
                unsigned b0 = __float_as_uint(Kt_s[(kc * 8 + t) * 72 + nt * 8 + g]);
                unsigned b1 = __float_as_uint(Kt_s[(kc * 8 + t + 4) * 72 + nt * 8 + g]);
                mma_tf32(s[nt], qa[kc], b0, b1);
            }
        }

        float pm0 = -INFINITY, pm1 = -INFINITY;
#pragma unroll
        for (int nt = 0; nt < 8; nt++) {
            pm0 = fmaxf(pm0, fmaxf(s[nt][0], s[nt][1]));
            pm1 = fmaxf(pm1, fmaxf(s[nt][2], s[nt][3]));
        }
        pm0 = fmaxf(pm0, __shfl_xor_sync(0xffffffffu, pm0, 1, 4));
        pm0 = fmaxf(pm0, __shfl_xor_sync(0xffffffffu, pm0, 2, 4));
        pm1 = fmaxf(pm1, __shfl_xor_sync(0xffffffffu, pm1, 1, 4));
        pm1 = fmaxf(pm1, __shfl_xor_sync(0xffffffffu, pm1, 2, 4));
        float mn0 = fmaxf(m0, pm0), mn1 = fmaxf(m1, pm1);
        float al0 = exp2f(m0 - mn0), al1 = exp2f(m1 - mn1);
        m0 = mn0; m1 = mn1;
        l0 *= al0; l1 *= al1;
#pragma unroll
        for (int c = 0; c < 4; c++) {
            o[c][0] *= al0; o[c][1] *= al0;
            o[c][2] *= al1; o[c][3] *= al1;
        }
        float ps0 = 0.f, ps1 = 0.f;
#pragma unroll
        for (int nt = 0; nt < 8; nt++) {
            float p0 = exp2f(s[nt][0] - mn0);
            float p1 = exp2f(s[nt][1] - mn0);
            float p2 = exp2f(s[nt][2] - mn1);
            float p3 = exp2f(s[nt][3] - mn1);
            ps0 += p0 + p1; ps1 += p2 + p3;
            uint2 lo = make_uint2(tf32_of(p0), tf32_of(p1));
            uint2 hi = make_uint2(tf32_of(p2), tf32_of(p3));
            *(uint2*)&Pw[g * 72 + nt * 8 + 2 * t] = lo;
            *(uint2*)&Pw[(g + 8) * 72 + nt * 8 + 2 * t] = hi;
        }
        ps0 += __shfl_xor_sync(0xffffffffu, ps0, 1, 4);
        ps0 += __shfl_xor_sync(0xffffffffu, ps0, 2, 4);
        ps1 += __shfl_xor_sync(0xffffffffu, ps1, 1, 4);
        ps1 += __shfl_xor_sync(0xffffffffu, ps1, 2, 4);
        l0 += ps0; l1 += ps1;
        __syncwarp();

#pragma unroll
        for (int c = 0; c < 8; c++) {
            unsigned pa[4];
            pa[0] = __float_as_uint(Pw[g * 72 + c * 8 + t]);
            pa[1] = __float_as_uint(Pw[(g + 8) * 72 + c * 8 + t]);
            pa[2] = __float_as_uint(Pw[g * 72 + c * 8 + t + 4]);
            pa[3] = __float_as_uint(Pw[(g + 8) * 72 + c * 8 + t + 4]);
#pragma unroll
            for (int nt2 = 0; nt2 < 4; nt2++) {
                unsigned b0 = __float_as_uint(Vs_s[(c * 8 + t) * 41 + nt2 * 8 + g]);
                unsigned b1 = __float_as_uint(Vs_s[(c * 8 + t + 4) * 41 + nt2 * 8 + g]);
                mma_tf32(o[nt2], pa, b0, b1);
            }
        }
        __syncwarp();
    }

    float inv0 = 1.f / l0, inv1 = 1.f / l1;
    float* av = g_av + (size_t)b * 32 * NPIX;
#pragma unroll
    for (int nt2 = 0; nt2 < 4; nt2++) {
        int ch = nt2 * 8 + 2 * t;
        av[(size_t)ch * NPIX + qrow]           = o[nt2][0] * inv0;
        av[(size_t)(ch + 1) * NPIX + qrow]     = o[nt2][1] * inv0;
        av[(size_t)ch * NPIX + qrow + 8]       = o[nt2][2] * inv1;
        av[(size_t)(ch + 1) * NPIX + qrow + 8] = o[nt2][3] * inv1;
    }
}

// ---------------- layernorm over 64 channels per pixel ----------------
__global__ void ln_kernel(const float* __restrict__ ln_g, const float* __restrict__ ln_b) {
    int p = blockIdx.x * 256 + threadIdx.x;
    int b = p >> 12, n = p & 4095;
    const float* ep = g_e + (size_t)b * 64 * NPIX + n;
    float v[64], mu = 0.f;
#pragma unroll
    for (int c = 0; c < 64; c++) { v[c] = ep[(size_t)c * NPIX]; mu += v[c]; }
    mu *= (1.f / 64.f);
    float var = 0.f;
#pragma unroll
    for (int c = 0; c < 64; c++) { float d = v[c] - mu; var += d * d; }
    var *= (1.f / 64.f);
    float inv = rsqrtf(var + 1e-5f);
    float* hp = g_h + (size_t)b * 64 * NPIX + n;
#pragma unroll
    for (int c = 0; c < 64; c++) hp[(size_t)c * NPIX] = (v[c] - mu) * inv * ln_g[c] + ln_b[c];
}

// ---------------- depthwise 3x3 conv + bias + GELU (4 px/thread, vectorized) ----------------
__global__ void dw_kernel(const float* __restrict__ dw_w, const float* __restrict__ dw_b) {
    int gid = blockIdx.x * 256 + threadIdx.x;          // 4*256*4096/4 = 1048576 groups
    int x4 = (gid & 15) * 4;
    int y = (gid >> 4) & 63;
    int c = (gid >> 10) & 255;
    int bc = gid >> 10;                                 // b*256 + c
    const float* hp = g_h1 + (size_t)bc * NPIX;
    const float* w = dw_w + c * 9;
    float a0 = 0.f, a1 = 0.f, a2 = 0.f, a3 = 0.f;
#pragma unroll
    for (int ky = 0; ky < 3; ky++) {
        int yy = y + ky - 1;
        if (yy < 0 || yy >= 64) continue;
        const float* row = hp + yy * 64;
        float4 m = *(const float4*)(row + x4);
        float vl = (x4 > 0) ? row[x4 - 1] : 0.f;
        float vr = (x4 + 4 < 64) ? row[x4 + 4] : 0.f;
        float w0 = w[ky * 3 + 0], w1 = w[ky * 3 + 1], w2 = w[ky * 3 + 2];
        // tap kx=0 (xx = x-1), kx=1 (xx = x), kx=2 (xx = x+1); zero pad handled by vl/vr
        a0 += w0 * vl;  a1 += w0 * m.x; a2 += w0 * m.y; a3 += w0 * m.z;
        a0 += w1 * m.x; a1 += w1 * m.y; a2 += w1 * m.z; a3 += w1 * m.w;
        a0 += w2 * m.y; a1 += w2 * m.z; a2 += w2 * m.w; a3 += w2 * vr;
    }
    float bb = dw_b[c];
    a0 += bb; a1 += bb; a2 += bb; a3 += bb;
    float4 r;
    r.x = a0 * normcdff(a0);
    r.y = a1 * normcdff(a1);
    r.z = a2 * normcdff(a2);
    r.w = a3 * normcdff(a3);
    *(float4*)&g_h2[(size_t)bc * NPIX + y * 64 + x4] = r;
}

// ---------------- host launcher ----------------
extern "C" void kernel_launch(void* const* d_in, const int* in_sizes, int n_in,
                              void* d_out, int out_size) {
    (void)in_sizes; (void)n_in; (void)out_size;
    const float* x       = (const float*)d_in[0];
    const float* skip    = (const float*)d_in[1];
    const float* qkv_w   = (const float*)d_in[2];
    const float* qkv_b   = (const float*)d_in[3];
    const float* proj_w  = (const float*)d_in[4];
    const float* proj_b  = (const float*)d_in[5];
    const float* edge_w  = (const float*)d_in[6];
    const float* thick_w = (const float*)d_in[7];
    const float* thick_b = (const float*)d_in[8];
    const float* off_w   = (const float*)d_in[9];
    const float* off_b   = (const float*)d_in[10];
    const float* deform_w= (const float*)d_in[11];
    const float* deform_b= (const float*)d_in[12];
    const float* ln_g    = (const float*)d_in[13];
    const float* ln_b    = (const float*)d_in[14];
    const float* mlp1_w  = (const float*)d_in[15];
    const float* mlp1_b  = (const float*)d_in[16];
    const float* dw_w    = (const float*)d_in[17];
    const float* dw_b    = (const float*)d_in[18];
    const float* mlp2_w  = (const float*)d_in[19];
    const float* mlp2_b  = (const float*)d_in[20];
    const float* down_w  = (const float*)d_in[21];
    const float* down_b  = (const float*)d_in[22];
    const float* up_w    = (const float*)d_in[23];
    const float* up_b    = (const float*)d_in[24];
    float* out = (float*)d_out;

    float *p_qkv, *p_av, *p_x2, *p_d, *p_e, *p_h, *p_h1, *p_h2, *p_t;
    float *p_qkvWT, *p_projWT, *p_downWT, *p_mlp1WT, *p_mlp2WT, *p_upWT;
    cudaGetSymbolAddress((void**)&p_qkv,    g_qkv);
    cudaGetSymbolAddress((void**)&p_av,     g_av);
    cudaGetSymbolAddress((void**)&p_x2,     g_x2);
    cudaGetSymbolAddress((void**)&p_d,      g_d);
    cudaGetSymbolAddress((void**)&p_e,      g_e);
    cudaGetSymbolAddress((void**)&p_h,      g_h);
    cudaGetSymbolAddress((void**)&p_h1,     g_h1);
    cudaGetSymbolAddress((void**)&p_h2,     g_h2);
    cudaGetSymbolAddress((void**)&p_t,      g_t);
    cudaGetSymbolAddress((void**)&p_qkvWT,  g_qkvWT);
    cudaGetSymbolAddress((void**)&p_projWT, g_projWT);
    cudaGetSymbolAddress((void**)&p_downWT, g_downWT);
    cudaGetSymbolAddress((void**)&p_mlp1WT, g_mlp1WT);
    cudaGetSymbolAddress((void**)&p_mlp2WT, g_mlp2WT);
    cudaGetSymbolAddress((void**)&p_upWT,   g_upWT);

    // one-time stream/event creation (host resources, not device memory).
    static cudaStream_t s1 = nullptr;
    static cudaEvent_t ev_fork = nullptr, ev_prep = nullptr, ev_join = nullptr;
    static int use_streams = -1;
    if (use_streams < 0) {
        cudaError_t e1 = cudaStreamCreateWithFlags(&s1, cudaStreamNonBlocking);
        cudaError_t e2 = cudaEventCreateWithFlags(&ev_fork, cudaEventDisableTiming);
        cudaError_t e3 = cudaEventCreateWithFlags(&ev_prep, cudaEventDisableTiming);
        cudaError_t e4 = cudaEventCreateWithFlags(&ev_join, cudaEventDisableTiming);
        use_streams = (e1 == cudaSuccess && e2 == cudaSuccess &&
                       e3 == cudaSuccess && e4 == cudaSuccess) ? 1 : 0;
        cudaFuncSetAttribute(flash_kernel, cudaFuncAttributeMaxDynamicSharedMemorySize,
                             FLASH_SM_FLOATS * 4);
    }
    const int flash_smem = FLASH_SM_FLOATS * 4;

    if (use_streams) {
        // fork immediately: upsample/edge/off don't need prepped weights
        cudaEventRecord(ev_fork, 0);
        cudaStreamWaitEvent(s1, ev_fork, 0);

        upsample_kernel<<<dim3(64, 4), 64, 0, s1>>>(skip, thick_w, thick_b);
        edge_kernel<<<4096, 256, 0, s1>>>(edge_w);
        off_kernel<<<128, 512, 0, s1>>>(off_w, off_b);

        // prep runs concurrently on default stream; deform (needs g_dwT) waits on it
        prep_kernel<<<128, 256>>>(qkv_w, proj_w, down_w, mlp1_w, mlp2_w, up_w, deform_w);
        cudaEventRecord(ev_prep, 0);
        cudaStreamWaitEvent(s1, ev_prep, 0);

        deform_kernel<<<256, 64, 0, s1>>>(deform_b);
        cudaEventRecord(ev_join, s1);

        gemm_tf32<<<dim3(128, 2), 256>>>(x, 256, nullptr, 256, p_qkvWT, qkv_b, 96, nullptr, p_qkv, 0);
        flash_kernel<<<dim3(32, 4), 256, flash_smem>>>();
        gemm_tf32<<<dim3(128, 4), 256>>>(p_av, 32, nullptr, 32, p_projWT, proj_b, 256, x, p_x2, 0);

        // join: down needs both x2 (default stream) and d (s1)
        cudaStreamWaitEvent(0, ev_join, 0);
    } else {
        upsample_kernel<<<dim3(64, 4), 64>>>(skip, thick_w, thick_b);
        edge_kernel<<<4096, 256>>>(edge_w);
        off_kernel<<<128, 512>>>(off_w, off_b);
        prep_kernel<<<128, 256>>>(qkv_w, proj_w, down_w, mlp1_w, mlp2_w, up_w, deform_w);
        deform_kernel<<<256, 64>>>(deform_b);
        gemm_tf32<<<dim3(128, 2), 256>>>(x, 256, nullptr, 256, p_qkvWT, qkv_b, 96, nullptr, p_qkv, 0);
        flash_kernel<<<dim3(32, 4), 256, flash_smem>>>();
        gemm_tf32<<<dim3(128, 4), 256>>>(p_av, 32, nullptr, 32, p_projWT, proj_b, 256, x, p_x2, 0);
    }

    gemm_tf32<<<dim3(128, 1), 256>>>(p_x2, 256, p_d, 320, p_downWT, down_b, 64, nullptr, p_e, 0);
    ln_kernel<<<64, 256>>>(ln_g, ln_b);
    gemm_tf32<<<dim3(128, 4), 256>>>(p_h, 64, nullptr, 64, p_mlp1WT, mlp1_b, 256, nullptr, p_h1, 1);
    dw_kernel<<<4096, 256>>>(dw_w, dw_b);
    gemm_tf32<<<dim3(128, 1), 256>>>(p_h2, 256, nullptr, 256, p_mlp2WT, mlp2_b, 64, p_e, p_t, 0);
    gemm_tf32<<<dim3(128, 4), 256>>>(p_t, 64, nullptr, 64, p_upWT, up_b, 256, nullptr, out, 0);
}